// round 1
// baseline (speedup 1.0000x reference)
#include <cuda_runtime.h>
#include <math.h>

#define NROWS 16384      // b*l = 4*4096
#define EMB   1024
#define HD    64
#define NBH   64         // b*h = 4*16
#define LSEQ  4096

// Scratch (device globals: allocation-free per harness rules)
__device__ float g_q[NROWS * EMB];
__device__ float g_k[NROWS * EMB];
__device__ float g_v[NROWS * EMB];
__device__ float g_u[NROWS * EMB];
__device__ float g_y[NROWS * EMB];
__device__ float g_kv[NBH * HD * HD];

// ---------------------------------------------------------------------------
// 128x128 fp32 SGEMM body: C[r,c] = act( sum_k A[r,k]*B[c,k] )
// Both A (16384x1024) and B (1024x1024) are row-major, K contiguous (NT GEMM).
// act: 0 = identity, 1 = relu(x)*0.125, 2 = silu
// ---------------------------------------------------------------------------
__device__ __forceinline__ void sgemm128(const float* __restrict__ A,
                                         const float* __restrict__ B,
                                         float* __restrict__ C, int act) {
    __shared__ float As[16][132];
    __shared__ float Bs[16][132];
    const int tid = threadIdx.x;
    const int tx = tid & 15;        // 16 col-thread groups
    const int ty = tid >> 4;        // 16 row-thread groups
    const int row0 = blockIdx.x * 128;
    const int col0 = blockIdx.y * 128;

    float acc[8][8];
#pragma unroll
    for (int i = 0; i < 8; i++)
#pragma unroll
        for (int j = 0; j < 8; j++) acc[i][j] = 0.0f;

    for (int k0 = 0; k0 < EMB; k0 += 16) {
        // Load 128x16 tiles of A and B, store k-transposed into smem.
#pragma unroll
        for (int i = 0; i < 2; i++) {
            int idx = tid + i * 256;           // 0..511 float4 ids
            int r   = idx >> 2;                // 0..127
            int kq  = (idx & 3) * 4;           // 0,4,8,12
            float4 av = *(const float4*)(A + (size_t)(row0 + r) * EMB + k0 + kq);
            As[kq + 0][r] = av.x; As[kq + 1][r] = av.y;
            As[kq + 2][r] = av.z; As[kq + 3][r] = av.w;
            float4 bv = *(const float4*)(B + (size_t)(col0 + r) * EMB + k0 + kq);
            Bs[kq + 0][r] = bv.x; Bs[kq + 1][r] = bv.y;
            Bs[kq + 2][r] = bv.z; Bs[kq + 3][r] = bv.w;
        }
        __syncthreads();

#pragma unroll
        for (int k = 0; k < 16; k++) {
            float a[8], b[8];
#pragma unroll
            for (int i = 0; i < 8; i++) a[i] = As[k][ty * 8 + i];
#pragma unroll
            for (int j = 0; j < 8; j++) b[j] = Bs[k][tx * 8 + j];
#pragma unroll
            for (int i = 0; i < 8; i++)
#pragma unroll
                for (int j = 0; j < 8; j++) acc[i][j] += a[i] * b[j];
        }
        __syncthreads();
    }

    // Epilogue with fused activation
#pragma unroll
    for (int i = 0; i < 8; i++) {
        size_t r = (size_t)(row0 + ty * 8 + i);
#pragma unroll
        for (int j4 = 0; j4 < 2; j4++) {
            float4 w;
            float v0 = acc[i][j4 * 4 + 0];
            float v1 = acc[i][j4 * 4 + 1];
            float v2 = acc[i][j4 * 4 + 2];
            float v3 = acc[i][j4 * 4 + 3];
            if (act == 1) {
                v0 = fmaxf(v0, 0.0f) * 0.125f; v1 = fmaxf(v1, 0.0f) * 0.125f;
                v2 = fmaxf(v2, 0.0f) * 0.125f; v3 = fmaxf(v3, 0.0f) * 0.125f;
            } else if (act == 2) {
                v0 = v0 / (1.0f + expf(-v0)); v1 = v1 / (1.0f + expf(-v1));
                v2 = v2 / (1.0f + expf(-v2)); v3 = v3 / (1.0f + expf(-v3));
            }
            w.x = v0; w.y = v1; w.z = v2; w.w = v3;
            *(float4*)(C + r * EMB + col0 + tx * 8 + j4 * 4) = w;
        }
    }
}

// ---------------------------------------------------------------------------
// Kernel 1: four projections fused over gridDim.z (q,k,v,u)
// ---------------------------------------------------------------------------
__global__ __launch_bounds__(256) void proj_kernel(const float* __restrict__ X,
                                                   const float* __restrict__ Wq,
                                                   const float* __restrict__ Wk,
                                                   const float* __restrict__ Wv,
                                                   const float* __restrict__ Wu) {
    int z = blockIdx.z;
    const float* W = (z == 0) ? Wq : (z == 1) ? Wk : (z == 2) ? Wv : Wu;
    float* O       = (z == 0) ? g_q : (z == 1) ? g_k : (z == 2) ? g_v : g_u;
    int act        = (z <= 1) ? 1 : (z == 2) ? 0 : 2;
    sgemm128(X, W, O, act);
}

// ---------------------------------------------------------------------------
// Kernel 0: zero the kv accumulator
// ---------------------------------------------------------------------------
__global__ void zero_kv_kernel() {
    int i = blockIdx.x * 256 + threadIdx.x;
    if (i < NBH * HD * HD) g_kv[i] = 0.0f;
}

// ---------------------------------------------------------------------------
// Kernel 2: kv[b,h] += sum_l k[b,h,l,:]^T v[b,h,l,:]  (split-L + atomicAdd)
// grid: (64 bh, 16 chunks of 256 l-rows), 256 threads, 4x4 microtile
// ---------------------------------------------------------------------------
__global__ __launch_bounds__(256) void kv_kernel() {
    const int bh = blockIdx.x;
    const int b  = bh >> 4;
    const int h  = bh & 15;
    const int lc = blockIdx.y;
    __shared__ float ks[32][64];
    __shared__ float vs[32][64];
    const int tid = threadIdx.x;
    const int tx = tid & 15;
    const int ty = tid >> 4;

    float acc[4][4];
#pragma unroll
    for (int i = 0; i < 4; i++)
#pragma unroll
        for (int j = 0; j < 4; j++) acc[i][j] = 0.0f;

    const size_t rowbase = (size_t)(b * LSEQ + lc * 256);
    for (int s = 0; s < 256; s += 32) {
#pragma unroll
        for (int i = 0; i < 2; i++) {
            int idx = tid + i * 256;           // 0..511 float4 ids
            int r = idx >> 4;                  // 0..31
            int c = (idx & 15) * 4;            // 0..60
            size_t off = (rowbase + s + r) * EMB + h * HD + c;
            *(float4*)&ks[r][c] = *(const float4*)(g_k + off);
            *(float4*)&vs[r][c] = *(const float4*)(g_v + off);
        }
        __syncthreads();
#pragma unroll
        for (int l = 0; l < 32; l++) {
            float a[4], bb[4];
#pragma unroll
            for (int i = 0; i < 4; i++) a[i] = ks[l][ty * 4 + i];
#pragma unroll
            for (int j = 0; j < 4; j++) bb[j] = vs[l][tx * 4 + j];
#pragma unroll
            for (int i = 0; i < 4; i++)
#pragma unroll
                for (int j = 0; j < 4; j++) acc[i][j] += a[i] * bb[j];
        }
        __syncthreads();
    }

    float* kvp = g_kv + (size_t)bh * HD * HD;
#pragma unroll
    for (int i = 0; i < 4; i++)
#pragma unroll
        for (int j = 0; j < 4; j++)
            atomicAdd(kvp + (ty * 4 + i) * HD + tx * 4 + j, acc[i][j]);
}

// ---------------------------------------------------------------------------
// Kernel 3: out = q @ kv; SRMSNorm over hd; * u; scatter into y
// grid: (64 bh, 16 tiles of 256 rows), 256 threads, one row per thread
// ---------------------------------------------------------------------------
__global__ __launch_bounds__(256) void outnorm_kernel() {
    const int bh = blockIdx.x;
    const int b  = bh >> 4;
    const int h  = bh & 15;
    const int lt = blockIdx.y;
    __shared__ float kvs[HD][HD];   // 16KB, 16B-aligned rows for LDS.128 broadcast
    const int tid = threadIdx.x;

    for (int i = tid; i < HD * HD; i += 256)
        kvs[i >> 6][i & 63] = g_kv[(size_t)bh * HD * HD + i];
    __syncthreads();

    const size_t row = (size_t)(b * LSEQ + lt * 256 + tid);
    const float* qp = g_q + row * EMB + h * HD;

    float qr[HD];
#pragma unroll
    for (int i = 0; i < 16; i++)
        *(float4*)&qr[i * 4] = *(const float4*)(qp + i * 4);

    float out[HD];
#pragma unroll
    for (int j = 0; j < HD; j++) out[j] = 0.0f;

#pragma unroll
    for (int kk = 0; kk < HD; kk++) {
        float qv = qr[kk];
#pragma unroll
        for (int j4 = 0; j4 < 16; j4++) {
            float4 kvv = *(const float4*)&kvs[kk][j4 * 4];
            out[j4 * 4 + 0] += qv * kvv.x;
            out[j4 * 4 + 1] += qv * kvv.y;
            out[j4 * 4 + 2] += qv * kvv.z;
            out[j4 * 4 + 3] += qv * kvv.w;
        }
    }

    float ss = 0.0f;
#pragma unroll
    for (int j = 0; j < HD; j++) ss += out[j] * out[j];
    float n   = sqrtf(ss) * 0.125f;           // ||out * (1/sqrt(64))||
    float inv = 1.0f / fmaxf(n, 1e-12f);

    const float* up = g_u + row * EMB + h * HD;
    float* yp       = g_y + row * EMB + h * HD;
#pragma unroll
    for (int i = 0; i < 16; i++) {
        float4 uv = *(const float4*)(up + i * 4);
        float4 w;
        w.x = out[i * 4 + 0] * inv * uv.x;
        w.y = out[i * 4 + 1] * inv * uv.y;
        w.z = out[i * 4 + 2] * inv * uv.z;
        w.w = out[i * 4 + 3] * inv * uv.w;
        *(float4*)(yp + i * 4) = w;
    }
}

// ---------------------------------------------------------------------------
// Kernel 4: final projection out = y @ Wo^T
// ---------------------------------------------------------------------------
__global__ __launch_bounds__(256) void final_kernel(const float* __restrict__ Wo,
                                                    float* __restrict__ out) {
    sgemm128(g_y, Wo, out, 0);
}

// ---------------------------------------------------------------------------
extern "C" void kernel_launch(void* const* d_in, const int* in_sizes, int n_in,
                              void* d_out, int out_size) {
    const float* x  = (const float*)d_in[0];
    const float* Wq = (const float*)d_in[1];
    const float* Wk = (const float*)d_in[2];
    const float* Wv = (const float*)d_in[3];
    const float* Wu = (const float*)d_in[4];
    const float* Wo = (const float*)d_in[5];
    float* out = (float*)d_out;

    zero_kv_kernel<<<(NBH * HD * HD + 255) / 256, 256>>>();
    proj_kernel<<<dim3(NROWS / 128, EMB / 128, 4), 256>>>(x, Wq, Wk, Wv, Wu);
    kv_kernel<<<dim3(NBH, LSEQ / 256), 256>>>();
    outnorm_kernel<<<dim3(NBH, LSEQ / 256), 256>>>();
    final_kernel<<<dim3(NROWS / 128, EMB / 128), 256>>>(Wo, out);
}

// round 4
// speedup vs baseline: 2.7825x; 2.7825x over previous
#include <cuda_runtime.h>
#include <cuda_bf16.h>
#include <math.h>
#include <stdint.h>

#define NROWS 16384      // b*l = 4*4096
#define EMB   1024
#define HD    64
#define NBH   64         // b*h
#define LSEQ  4096
#define KT    16         // K tiles of 64
#define TILE_ELEMS 8192  // 128 rows * 64 bf16
#define TILE_BYTES 16384
#define WSZ (8*16*8192)  // per-weight tiled elems (1024*1024)
#define STAGES 3
#define STAGE_BYTES (4*TILE_BYTES)   // Ah|Al|Bh|Bl
#define GSMEM (STAGES*STAGE_BYTES)   // 196608

using bf16 = __nv_bfloat16;

// ---------------- scratch (device globals; allocation-free) ----------------
__device__ __align__(128) float g_q[NROWS * EMB];
__device__ __align__(128) float g_k[NROWS * EMB];
__device__ __align__(128) float g_v[NROWS * EMB];
__device__ __align__(128) float g_u[NROWS * EMB];
__device__ __align__(128) float g_kv[NBH * HD * HD];
__device__ __align__(128) bf16  g_xh[NROWS * EMB];
__device__ __align__(128) bf16  g_xl[NROWS * EMB];
__device__ __align__(128) bf16  g_yh[NROWS * EMB];
__device__ __align__(128) bf16  g_yl[NROWS * EMB];
__device__ __align__(128) bf16  g_wh[5 * WSZ];
__device__ __align__(128) bf16  g_wl[5 * WSZ];

// ---------------- helpers ----------------
__device__ __forceinline__ uint32_t s2u(const void* p) {
    uint32_t a;
    asm("{ .reg .u64 t; cvta.to.shared.u64 t, %1; cvt.u32.u64 %0, t; }" : "=r"(a) : "l"(p));
    return a;
}
__device__ __forceinline__ uint32_t swz(uint32_t off) { return off ^ ((off >> 3) & 0x70); }

__device__ __forceinline__ void cpa16(uint32_t saddr, const void* gaddr) {
    asm volatile("cp.async.cg.shared.global [%0], [%1], 16;" :: "r"(saddr), "l"(gaddr) : "memory");
}
__device__ __forceinline__ void cpa_commit() {
    asm volatile("cp.async.commit_group;" ::: "memory");
}
__device__ __forceinline__ void cpa_wait1() {
    asm volatile("cp.async.wait_group 1;" ::: "memory");
}
__device__ __forceinline__ void cpa_wait0() {
    asm volatile("cp.async.wait_group 0;" ::: "memory");
}
__device__ __forceinline__ void ldsm4(uint32_t& r0, uint32_t& r1, uint32_t& r2, uint32_t& r3,
                                      uint32_t addr) {
    asm volatile("ldmatrix.sync.aligned.m8n8.x4.shared.b16 {%0,%1,%2,%3}, [%4];"
                 : "=r"(r0), "=r"(r1), "=r"(r2), "=r"(r3) : "r"(addr));
}
__device__ __forceinline__ void mma16816(float* c, uint32_t a0, uint32_t a1, uint32_t a2,
                                         uint32_t a3, uint32_t b0, uint32_t b1) {
    asm volatile(
        "mma.sync.aligned.m16n8k16.row.col.f32.bf16.bf16.f32 "
        "{%0,%1,%2,%3},{%4,%5,%6,%7},{%8,%9},{%0,%1,%2,%3};"
        : "+f"(c[0]), "+f"(c[1]), "+f"(c[2]), "+f"(c[3])
        : "r"(a0), "r"(a1), "r"(a2), "r"(a3), "r"(b0), "r"(b1));
}

// split 8 fp32 -> hi/lo bf16 packed 16B each
__device__ __forceinline__ void split8(const float* v, uint4& h, uint4& l) {
    unsigned int hu[4], lu[4];
#pragma unroll
    for (int j = 0; j < 4; j++) {
        float a = v[2 * j], b = v[2 * j + 1];
        bf16 ah = __float2bfloat16_rn(a), bh = __float2bfloat16_rn(b);
        float ar = a - __bfloat162float(ah), br = b - __bfloat162float(bh);
        bf16 al = __float2bfloat16_rn(ar), bl = __float2bfloat16_rn(br);
        hu[j] = (unsigned)__bfloat16_as_ushort(ah) | ((unsigned)__bfloat16_as_ushort(bh) << 16);
        lu[j] = (unsigned)__bfloat16_as_ushort(al) | ((unsigned)__bfloat16_as_ushort(bl) << 16);
    }
    h = make_uint4(hu[0], hu[1], hu[2], hu[3]);
    l = make_uint4(lu[0], lu[1], lu[2], lu[3]);
}

// ---------------- convert kernels (tiled SW128 split layout) ----------------
__global__ __launch_bounds__(256) void split_x_kernel(const float* __restrict__ X) {
    int i = blockIdx.x * 256 + threadIdx.x;      // 0 .. 16384*128-1
    int row = i >> 7, c = i & 127;
    int kt = c >> 3, ci = c & 7;
    const float4* p = (const float4*)(X + (size_t)row * EMB + kt * 64 + ci * 8);
    float vv[8];
    *(float4*)&vv[0] = p[0];
    *(float4*)&vv[4] = p[1];
    uint4 h, l;
    split8(vv, h, l);
    int mt = row >> 7, r = row & 127;
    uint32_t off = swz(r * 128 + ci * 16);
    size_t base = ((size_t)(mt * KT + kt)) * TILE_ELEMS;
    *(uint4*)((char*)g_xh + base * 2 + off) = h;
    *(uint4*)((char*)g_xl + base * 2 + off) = l;
}

__global__ __launch_bounds__(256) void split_w_kernel(const float* __restrict__ Wq,
                                                      const float* __restrict__ Wk,
                                                      const float* __restrict__ Wv,
                                                      const float* __restrict__ Wu,
                                                      const float* __restrict__ Wo) {
    int i = blockIdx.x * 256 + threadIdx.x;      // 0 .. 5120*128-1
    int row = i >> 7, c = i & 127;
    int widx = row >> 10, r = row & 1023;
    int kt = c >> 3, ci = c & 7;
    const float* W = (widx == 0) ? Wq : (widx == 1) ? Wk : (widx == 2) ? Wv : (widx == 3) ? Wu : Wo;
    const float4* p = (const float4*)(W + (size_t)r * EMB + kt * 64 + ci * 8);
    float vv[8];
    *(float4*)&vv[0] = p[0];
    *(float4*)&vv[4] = p[1];
    uint4 h, l;
    split8(vv, h, l);
    int nt = r >> 7, rr = r & 127;
    uint32_t off = swz(rr * 128 + ci * 16);
    size_t base = (size_t)widx * WSZ + ((size_t)(nt * KT + kt)) * TILE_ELEMS;
    *(uint4*)((char*)g_wh + base * 2 + off) = h;
    *(uint4*)((char*)g_wl + base * 2 + off) = l;
}

// ---------------- mma.sync GEMM core: 128x128 CTA, BK=64, 3-stage ----------
// Stage layout: Ah(16K) Al(16K) Bh(16K) Bl(16K). Tiled globals are linear 16KB
// per (tile, kchunk) and already SW128-swizzled -> stage copies are linear.
__device__ __forceinline__ void gemm_mma(const bf16* __restrict__ Ahg,
                                         const bf16* __restrict__ Alg,
                                         const bf16* __restrict__ Bhg,
                                         const bf16* __restrict__ Blg,
                                         float* __restrict__ C, int act) {
    extern __shared__ char sm[];
    uint32_t sb = s2u(sm);
    const int tid = threadIdx.x, lane = tid & 31, wid = tid >> 5;
    const int mt = blockIdx.x, nt = blockIdx.y;
    const int warpM = (wid >> 2) * 64;    // 0 / 64
    const int warpN = (wid & 3) * 32;     // 0,32,64,96

    // per-thread stage source bases (element offsets into tiled arrays)
    auto load_stage = [&](int s, int kc) {
        uint32_t d = sb + s * STAGE_BYTES;
        size_t at = ((size_t)(mt * KT + kc)) * TILE_ELEMS;
        size_t bt = ((size_t)(nt * KT + kc)) * TILE_ELEMS;
        const char* srcs[4] = {(const char*)(Ahg + at), (const char*)(Alg + at),
                               (const char*)(Bhg + bt), (const char*)(Blg + bt)};
#pragma unroll
        for (int blk = 0; blk < 4; blk++)
#pragma unroll
            for (int i = 0; i < 4; i++)
                cpa16(d + blk * TILE_BYTES + i * 4096 + tid * 16,
                      srcs[blk] + i * 4096 + tid * 16);
        cpa_commit();
    };

    float acc[4][4][4];
#pragma unroll
    for (int i = 0; i < 4; i++)
#pragma unroll
        for (int j = 0; j < 4; j++)
#pragma unroll
            for (int e = 0; e < 4; e++) acc[i][j][e] = 0.0f;

    // fragment address components (within a 16KB tile)
    const int aRow = warpM + (lane & 15);          // + i*16
    const int aKg  = (lane >> 4);                  // + kk*2
    const int bRow = warpN + ((lane >> 4) << 3) + (lane & 7);   // + jj*8
    const int bKg  = ((lane >> 3) & 1);            // + kk*2

    load_stage(0, 0);
    load_stage(1, 1);

    for (int kc = 0; kc < KT; kc++) {
        int s = kc % STAGES;
        if (kc + 1 < KT) cpa_wait1(); else cpa_wait0();
        __syncthreads();
        if (kc + 2 < KT) load_stage((kc + 2) % STAGES, kc + 2);

        uint32_t Ah = sb + s * STAGE_BYTES;
        uint32_t Al = Ah + TILE_BYTES;
        uint32_t Bh = Ah + 2 * TILE_BYTES;
        uint32_t Bl = Ah + 3 * TILE_BYTES;

#pragma unroll
        for (int kk = 0; kk < 4; kk++) {
            uint32_t aoff[4], boff[2];
#pragma unroll
            for (int i = 0; i < 4; i++)
                aoff[i] = swz((aRow + i * 16) * 128 + (kk * 2 + aKg) * 16);
#pragma unroll
            for (int jj = 0; jj < 2; jj++)
                boff[jj] = swz((bRow + jj * 16) * 128 + (kk * 2 + bKg) * 16);

            uint32_t aH[4][4], aL[4][4], bH[4][2], bL[4][2];
#pragma unroll
            for (int i = 0; i < 4; i++)
                ldsm4(aH[i][0], aH[i][1], aH[i][2], aH[i][3], Ah + aoff[i]);
#pragma unroll
            for (int jj = 0; jj < 2; jj++)
                ldsm4(bH[2 * jj][0], bH[2 * jj][1], bH[2 * jj + 1][0], bH[2 * jj + 1][1],
                      Bh + boff[jj]);
#pragma unroll
            for (int i = 0; i < 4; i++)
#pragma unroll
                for (int j = 0; j < 4; j++)
                    mma16816(acc[i][j], aH[i][0], aH[i][1], aH[i][2], aH[i][3],
                             bH[j][0], bH[j][1]);

#pragma unroll
            for (int jj = 0; jj < 2; jj++)
                ldsm4(bL[2 * jj][0], bL[2 * jj][1], bL[2 * jj + 1][0], bL[2 * jj + 1][1],
                      Bl + boff[jj]);
#pragma unroll
            for (int i = 0; i < 4; i++)
#pragma unroll
                for (int j = 0; j < 4; j++)
                    mma16816(acc[i][j], aH[i][0], aH[i][1], aH[i][2], aH[i][3],
                             bL[j][0], bL[j][1]);

#pragma unroll
            for (int i = 0; i < 4; i++)
                ldsm4(aL[i][0], aL[i][1], aL[i][2], aL[i][3], Al + aoff[i]);
#pragma unroll
            for (int i = 0; i < 4; i++)
#pragma unroll
                for (int j = 0; j < 4; j++)
                    mma16816(acc[i][j], aL[i][0], aL[i][1], aL[i][2], aL[i][3],
                             bH[j][0], bH[j][1]);
        }
    }

    // epilogue: c frag thread layout: (row = lane>>2 [+8], col = (lane&3)*2 +{0,1})
#pragma unroll
    for (int i = 0; i < 4; i++) {
#pragma unroll
        for (int j = 0; j < 4; j++) {
#pragma unroll
            for (int half = 0; half < 2; half++) {
                int row = mt * 128 + warpM + i * 16 + (lane >> 2) + half * 8;
                int col = nt * 128 + warpN + j * 8 + (lane & 3) * 2;
                float v0 = acc[i][j][half * 2 + 0];
                float v1 = acc[i][j][half * 2 + 1];
                if (act == 1) {
                    v0 = fmaxf(v0, 0.f) * 0.125f;
                    v1 = fmaxf(v1, 0.f) * 0.125f;
                } else if (act == 2) {
                    v0 = v0 / (1.f + expf(-v0));
                    v1 = v1 / (1.f + expf(-v1));
                }
                float2 w = make_float2(v0, v1);
                *(float2*)(C + (size_t)row * EMB + col) = w;
            }
        }
    }
}

__global__ __launch_bounds__(256, 1) void proj_mma() {
    int z = blockIdx.z;
    float* C = (z == 0) ? g_q : (z == 1) ? g_k : (z == 2) ? g_v : g_u;
    int act  = (z <= 1) ? 1 : (z == 2) ? 0 : 2;
    gemm_mma(g_xh, g_xl, g_wh + (size_t)z * WSZ, g_wl + (size_t)z * WSZ, C, act);
}

__global__ __launch_bounds__(256, 1) void fin_mma(float* __restrict__ out) {
    gemm_mma(g_yh, g_yl, g_wh + (size_t)4 * WSZ, g_wl + (size_t)4 * WSZ, out, 0);
}

// ---------------- kv accumulation ----------------
__global__ void zero_kv_kernel() {
    int i = blockIdx.x * 256 + threadIdx.x;
    if (i < NBH * HD * HD) g_kv[i] = 0.0f;
}

__global__ __launch_bounds__(256) void kv_kernel() {
    const int bh = blockIdx.x;
    const int b = bh >> 4;
    const int h = bh & 15;
    const int lc = blockIdx.y;
    __shared__ float ks[32][64];
    __shared__ float vs[32][64];
    const int tid = threadIdx.x;
    const int tx = tid & 15;
    const int ty = tid >> 4;

    float acc[4][4];
#pragma unroll
    for (int i = 0; i < 4; i++)
#pragma unroll
        for (int j = 0; j < 4; j++) acc[i][j] = 0.0f;

    const size_t rowbase = (size_t)(b * LSEQ + lc * 256);
    for (int s = 0; s < 256; s += 32) {
#pragma unroll
        for (int i = 0; i < 2; i++) {
            int idx = tid + i * 256;
            int r = idx >> 4;
            int c = (idx & 15) * 4;
            size_t off = (rowbase + s + r) * EMB + h * HD + c;
            *(float4*)&ks[r][c] = *(const float4*)(g_k + off);
            *(float4*)&vs[r][c] = *(const float4*)(g_v + off);
        }
        __syncthreads();
#pragma unroll
        for (int l = 0; l < 32; l++) {
            float a[4], bb[4];
#pragma unroll
            for (int i = 0; i < 4; i++) a[i] = ks[l][ty * 4 + i];
#pragma unroll
            for (int j = 0; j < 4; j++) bb[j] = vs[l][tx * 4 + j];
#pragma unroll
            for (int i = 0; i < 4; i++)
#pragma unroll
                for (int j = 0; j < 4; j++) acc[i][j] += a[i] * bb[j];
        }
        __syncthreads();
    }

    float* kvp = g_kv + (size_t)bh * HD * HD;
#pragma unroll
    for (int i = 0; i < 4; i++)
#pragma unroll
        for (int j = 0; j < 4; j++)
            atomicAdd(kvp + (ty * 4 + i) * HD + tx * 4 + j, acc[i][j]);
}

// ---------------- out = q @ kv; SRMSNorm; * u; write split bf16 y ----------
__global__ __launch_bounds__(256) void outnorm_kernel() {
    const int bh = blockIdx.x;
    const int b = bh >> 4;
    const int h = bh & 15;
    const int lt = blockIdx.y;
    __shared__ float kvs[HD][HD];
    const int tid = threadIdx.x;

    for (int i = tid; i < HD * HD; i += 256)
        kvs[i >> 6][i & 63] = g_kv[(size_t)bh * HD * HD + i];
    __syncthreads();

    const int row = b * LSEQ + lt * 256 + tid;
    const float* qp = g_q + (size_t)row * EMB + h * HD;

    float qr[HD];
#pragma unroll
    for (int i = 0; i < 16; i++)
        *(float4*)&qr[i * 4] = *(const float4*)(qp + i * 4);

    float out[HD];
#pragma unroll
    for (int j = 0; j < HD; j++) out[j] = 0.0f;

#pragma unroll
    for (int kk = 0; kk < HD; kk++) {
        float qv = qr[kk];
#pragma unroll
        for (int j4 = 0; j4 < 16; j4++) {
            float4 kvv = *(const float4*)&kvs[kk][j4 * 4];
            out[j4 * 4 + 0] += qv * kvv.x;
            out[j4 * 4 + 1] += qv * kvv.y;
            out[j4 * 4 + 2] += qv * kvv.z;
            out[j4 * 4 + 3] += qv * kvv.w;
        }
    }

    float ss = 0.0f;
#pragma unroll
    for (int j = 0; j < HD; j++) ss += out[j] * out[j];
    float n = sqrtf(ss) * 0.125f;
    float inv = 1.0f / fmaxf(n, 1e-12f);

    const float* up = g_u + (size_t)row * EMB + h * HD;
#pragma unroll
    for (int i = 0; i < 16; i++) {
        float4 uv = *(const float4*)(up + i * 4);
        out[i * 4 + 0] *= inv * uv.x;
        out[i * 4 + 1] *= inv * uv.y;
        out[i * 4 + 2] *= inv * uv.z;
        out[i * 4 + 3] *= inv * uv.w;
    }

    // write split bf16 y into tiled swizzled layout (ktile == h)
    int mt = row >> 7, r = row & 127;
    size_t base = ((size_t)(mt * KT + h)) * TILE_ELEMS;
#pragma unroll
    for (int ci = 0; ci < 8; ci++) {
        uint4 hh, ll;
        split8(&out[ci * 8], hh, ll);
        uint32_t off = swz(r * 128 + ci * 16);
        *(uint4*)((char*)g_yh + base * 2 + off) = hh;
        *(uint4*)((char*)g_yl + base * 2 + off) = ll;
    }
}

// ---------------------------------------------------------------------------
extern "C" void kernel_launch(void* const* d_in, const int* in_sizes, int n_in,
                              void* d_out, int out_size) {
    const float* x  = (const float*)d_in[0];
    const float* Wq = (const float*)d_in[1];
    const float* Wk = (const float*)d_in[2];
    const float* Wv = (const float*)d_in[3];
    const float* Wu = (const float*)d_in[4];
    const float* Wo = (const float*)d_in[5];
    float* out = (float*)d_out;

    cudaFuncSetAttribute(proj_mma, cudaFuncAttributeMaxDynamicSharedMemorySize, GSMEM);
    cudaFuncSetAttribute(fin_mma,  cudaFuncAttributeMaxDynamicSharedMemorySize, GSMEM);

    split_x_kernel<<<8192, 256>>>(x);
    split_w_kernel<<<2560, 256>>>(Wq, Wk, Wv, Wu, Wo);
    zero_kv_kernel<<<(NBH * HD * HD + 255) / 256, 256>>>();
    proj_mma<<<dim3(128, 8, 4), 256, GSMEM>>>();
    kv_kernel<<<dim3(NBH, LSEQ / 256), 256>>>();
    outnorm_kernel<<<dim3(NBH, LSEQ / 256), 256>>>();
    fin_mma<<<dim3(128, 8), 256, GSMEM>>>(out);
}

// round 5
// speedup vs baseline: 3.7340x; 1.3420x over previous
#include <cuda_runtime.h>
#include <cuda_fp16.h>
#include <math.h>
#include <stdint.h>

#define NROWS 16384      // b*l = 4*4096
#define EMB   1024
#define HD    64
#define NBH   64         // b*h
#define LSEQ  4096
#define KT    16         // K chunks of 64
#define TILE_ELEMS 8192  // 128 rows * 64 fp16
#define TILE_BYTES 16384
#define WSZ (8*16*8192)  // per-weight tiled elems (1024*1024)
#define STAGES 4
#define STAGE_BYTES (3*TILE_BYTES)   // A | Bh | Bl = 48KB
#define GSMEM (STAGES*STAGE_BYTES)   // 196608

using f16 = __half;

// ---------------- scratch (device globals; allocation-free) ----------------
__device__ __align__(128) float g_q[NROWS * EMB];
__device__ __align__(128) float g_k[NROWS * EMB];
__device__ __align__(128) float g_v[NROWS * EMB];
__device__ __align__(128) float g_u[NROWS * EMB];
__device__ __align__(128) float g_kv[NBH * HD * HD];
__device__ __align__(128) f16   g_xf[NROWS * EMB];    // x, fp16 tiled
__device__ __align__(128) f16   g_yf[NROWS * EMB];    // y, fp16 tiled
__device__ __align__(128) f16   g_wh[5 * WSZ];        // W hi fp16 tiled
__device__ __align__(128) f16   g_wl[5 * WSZ];        // W lo fp16 tiled

// ---------------- helpers ----------------
__device__ __forceinline__ uint32_t s2u(const void* p) {
    uint32_t a;
    asm("{ .reg .u64 t; cvta.to.shared.u64 t, %1; cvt.u32.u64 %0, t; }" : "=r"(a) : "l"(p));
    return a;
}
__device__ __forceinline__ uint32_t swz(uint32_t off) { return off ^ ((off >> 3) & 0x70); }

__device__ __forceinline__ void cpa16(uint32_t saddr, const void* gaddr) {
    asm volatile("cp.async.cg.shared.global [%0], [%1], 16;" :: "r"(saddr), "l"(gaddr) : "memory");
}
__device__ __forceinline__ void cpa_commit() {
    asm volatile("cp.async.commit_group;" ::: "memory");
}
__device__ __forceinline__ void cpa_wait2() {
    asm volatile("cp.async.wait_group 2;" ::: "memory");
}
__device__ __forceinline__ void cpa_wait1() {
    asm volatile("cp.async.wait_group 1;" ::: "memory");
}
__device__ __forceinline__ void cpa_wait0() {
    asm volatile("cp.async.wait_group 0;" ::: "memory");
}
__device__ __forceinline__ void ldsm4(uint32_t& r0, uint32_t& r1, uint32_t& r2, uint32_t& r3,
                                      uint32_t addr) {
    asm volatile("ldmatrix.sync.aligned.m8n8.x4.shared.b16 {%0,%1,%2,%3}, [%4];"
                 : "=r"(r0), "=r"(r1), "=r"(r2), "=r"(r3) : "r"(addr));
}
__device__ __forceinline__ void mma16816(float* c, uint32_t a0, uint32_t a1, uint32_t a2,
                                         uint32_t a3, uint32_t b0, uint32_t b1) {
    asm volatile(
        "mma.sync.aligned.m16n8k16.row.col.f32.f16.f16.f32 "
        "{%0,%1,%2,%3},{%4,%5,%6,%7},{%8,%9},{%0,%1,%2,%3};"
        : "+f"(c[0]), "+f"(c[1]), "+f"(c[2]), "+f"(c[3])
        : "r"(a0), "r"(a1), "r"(a2), "r"(a3), "r"(b0), "r"(b1));
}

// pack 8 fp32 -> 8 fp16 (16B)
__device__ __forceinline__ uint4 conv8h(const float* v) {
    unsigned int u[4];
#pragma unroll
    for (int j = 0; j < 4; j++) {
        u[j] = (unsigned)__half_as_ushort(__float2half_rn(v[2 * j])) |
               ((unsigned)__half_as_ushort(__float2half_rn(v[2 * j + 1])) << 16);
    }
    return make_uint4(u[0], u[1], u[2], u[3]);
}
// split 8 fp32 -> hi/lo fp16 packed 16B each
__device__ __forceinline__ void split8h(const float* v, uint4& h, uint4& l) {
    unsigned int hu[4], lu[4];
#pragma unroll
    for (int j = 0; j < 4; j++) {
        float a = v[2 * j], b = v[2 * j + 1];
        f16 ah = __float2half_rn(a), bh = __float2half_rn(b);
        float ar = a - __half2float(ah), br = b - __half2float(bh);
        f16 al = __float2half_rn(ar), bl = __float2half_rn(br);
        hu[j] = (unsigned)__half_as_ushort(ah) | ((unsigned)__half_as_ushort(bh) << 16);
        lu[j] = (unsigned)__half_as_ushort(al) | ((unsigned)__half_as_ushort(bl) << 16);
    }
    h = make_uint4(hu[0], hu[1], hu[2], hu[3]);
    l = make_uint4(lu[0], lu[1], lu[2], lu[3]);
}

// ---------------- convert kernels (tiled SW128 layout) ----------------
__global__ __launch_bounds__(256) void split_x_kernel(const float* __restrict__ X) {
    int i = blockIdx.x * 256 + threadIdx.x;      // 0 .. 16384*128-1
    int row = i >> 7, c = i & 127;
    int kt = c >> 3, ci = c & 7;
    const float4* p = (const float4*)(X + (size_t)row * EMB + kt * 64 + ci * 8);
    float vv[8];
    *(float4*)&vv[0] = p[0];
    *(float4*)&vv[4] = p[1];
    uint4 h = conv8h(vv);
    int mt = row >> 7, r = row & 127;
    uint32_t off = swz(r * 128 + ci * 16);
    size_t base = ((size_t)(mt * KT + kt)) * TILE_ELEMS;
    *(uint4*)((char*)g_xf + base * 2 + off) = h;
}

__global__ __launch_bounds__(256) void split_w_kernel(const float* __restrict__ Wq,
                                                      const float* __restrict__ Wk,
                                                      const float* __restrict__ Wv,
                                                      const float* __restrict__ Wu,
                                                      const float* __restrict__ Wo) {
    int i = blockIdx.x * 256 + threadIdx.x;      // 0 .. 5120*128-1
    int row = i >> 7, c = i & 127;
    int widx = row >> 10, r = row & 1023;
    int kt = c >> 3, ci = c & 7;
    const float* W = (widx == 0) ? Wq : (widx == 1) ? Wk : (widx == 2) ? Wv : (widx == 3) ? Wu : Wo;
    const float4* p = (const float4*)(W + (size_t)r * EMB + kt * 64 + ci * 8);
    float vv[8];
    *(float4*)&vv[0] = p[0];
    *(float4*)&vv[4] = p[1];
    uint4 h, l;
    split8h(vv, h, l);
    int nt = r >> 7, rr = r & 127;
    uint32_t off = swz(rr * 128 + ci * 16);
    size_t base = (size_t)widx * WSZ + ((size_t)(nt * KT + kt)) * TILE_ELEMS;
    *(uint4*)((char*)g_wh + base * 2 + off) = h;
    *(uint4*)((char*)g_wl + base * 2 + off) = l;
}

// ---------------- mma.sync GEMM core: 128x128 CTA, BK=64, 4-stage ----------
// Stage layout: A(16K) Bh(16K) Bl(16K). 2 products: A*Bh + A*Bl.
__device__ __forceinline__ void gemm_mma(const f16* __restrict__ Ag,
                                         const f16* __restrict__ Bhg,
                                         const f16* __restrict__ Blg,
                                         float* __restrict__ C, int act) {
    extern __shared__ char sm[];
    uint32_t sb = s2u(sm);
    const int tid = threadIdx.x, lane = tid & 31, wid = tid >> 5;
    const int mt = blockIdx.x, nt = blockIdx.y;
    const int warpM = (wid >> 2) * 64;    // 0 / 64
    const int warpN = (wid & 3) * 32;     // 0,32,64,96

    auto load_stage = [&](int s, int kc) {
        uint32_t d = sb + s * STAGE_BYTES;
        size_t at = ((size_t)(mt * KT + kc)) * TILE_ELEMS;
        size_t bt = ((size_t)(nt * KT + kc)) * TILE_ELEMS;
        const char* srcs[3] = {(const char*)(Ag + at), (const char*)(Bhg + bt),
                               (const char*)(Blg + bt)};
#pragma unroll
        for (int blk = 0; blk < 3; blk++)
#pragma unroll
            for (int i = 0; i < 4; i++)
                cpa16(d + blk * TILE_BYTES + i * 4096 + tid * 16,
                      srcs[blk] + i * 4096 + tid * 16);
        cpa_commit();
    };

    float acc[4][4][4];
#pragma unroll
    for (int i = 0; i < 4; i++)
#pragma unroll
        for (int j = 0; j < 4; j++)
#pragma unroll
            for (int e = 0; e < 4; e++) acc[i][j][e] = 0.0f;

    const int aRow = warpM + (lane & 15);                       // + i*16
    const int aKg  = (lane >> 4);                               // + kk*2
    const int bRow = warpN + ((lane >> 4) << 3) + (lane & 7);   // + jj*16
    const int bKg  = ((lane >> 3) & 1);                         // + kk*2

    uint32_t aX[2][4][4], bH[2][4][2], bL[2][4][2];

    load_stage(0, 0);
    load_stage(1, 1);
    load_stage(2, 2);

    for (int kc = 0; kc < KT; kc++) {
        int s = kc % STAGES;
        if (kc + 2 < KT) cpa_wait2();
        else if (kc + 1 < KT) cpa_wait1();
        else cpa_wait0();
        __syncthreads();
        if (kc + 3 < KT) load_stage((kc + 3) % STAGES, kc + 3);

        uint32_t A  = sb + s * STAGE_BYTES;
        uint32_t Bh = A + TILE_BYTES;
        uint32_t Bl = A + 2 * TILE_BYTES;

        auto ld_frags = [&](int kk, int buf) {
#pragma unroll
            for (int i = 0; i < 4; i++)
                ldsm4(aX[buf][i][0], aX[buf][i][1], aX[buf][i][2], aX[buf][i][3],
                      A + swz((aRow + i * 16) * 128 + (kk * 2 + aKg) * 16));
#pragma unroll
            for (int jj = 0; jj < 2; jj++) {
                uint32_t boff = swz((bRow + jj * 16) * 128 + (kk * 2 + bKg) * 16);
                ldsm4(bH[buf][2 * jj][0], bH[buf][2 * jj][1],
                      bH[buf][2 * jj + 1][0], bH[buf][2 * jj + 1][1], Bh + boff);
                ldsm4(bL[buf][2 * jj][0], bL[buf][2 * jj][1],
                      bL[buf][2 * jj + 1][0], bL[buf][2 * jj + 1][1], Bl + boff);
            }
        };

        ld_frags(0, 0);
#pragma unroll
        for (int kk = 0; kk < 4; kk++) {
            int cur = kk & 1;
            if (kk < 3) ld_frags(kk + 1, cur ^ 1);
#pragma unroll
            for (int i = 0; i < 4; i++)
#pragma unroll
                for (int j = 0; j < 4; j++)
                    mma16816(acc[i][j], aX[cur][i][0], aX[cur][i][1], aX[cur][i][2],
                             aX[cur][i][3], bH[cur][j][0], bH[cur][j][1]);
#pragma unroll
            for (int i = 0; i < 4; i++)
#pragma unroll
                for (int j = 0; j < 4; j++)
                    mma16816(acc[i][j], aX[cur][i][0], aX[cur][i][1], aX[cur][i][2],
                             aX[cur][i][3], bL[cur][j][0], bL[cur][j][1]);
        }
    }

    // epilogue
#pragma unroll
    for (int i = 0; i < 4; i++) {
#pragma unroll
        for (int j = 0; j < 4; j++) {
#pragma unroll
            for (int half = 0; half < 2; half++) {
                int row = mt * 128 + warpM + i * 16 + (lane >> 2) + half * 8;
                int col = nt * 128 + warpN + j * 8 + (lane & 3) * 2;
                float v0 = acc[i][j][half * 2 + 0];
                float v1 = acc[i][j][half * 2 + 1];
                if (act == 1) {
                    v0 = fmaxf(v0, 0.f) * 0.125f;
                    v1 = fmaxf(v1, 0.f) * 0.125f;
                } else if (act == 2) {
                    v0 = v0 / (1.f + expf(-v0));
                    v1 = v1 / (1.f + expf(-v1));
                }
                *(float2*)(C + (size_t)row * EMB + col) = make_float2(v0, v1);
            }
        }
    }
}

__global__ __launch_bounds__(256, 1) void proj_mma() {
    int z = blockIdx.z;
    float* C = (z == 0) ? g_q : (z == 1) ? g_k : (z == 2) ? g_v : g_u;
    int act  = (z <= 1) ? 1 : (z == 2) ? 0 : 2;
    gemm_mma(g_xf, g_wh + (size_t)z * WSZ, g_wl + (size_t)z * WSZ, C, act);
}

__global__ __launch_bounds__(256, 1) void fin_mma(float* __restrict__ out) {
    gemm_mma(g_yf, g_wh + (size_t)4 * WSZ, g_wl + (size_t)4 * WSZ, out, 0);
}

// ---------------- kv accumulation ----------------
__global__ void zero_kv_kernel() {
    int i = blockIdx.x * 256 + threadIdx.x;
    if (i < NBH * HD * HD) g_kv[i] = 0.0f;
}

__global__ __launch_bounds__(256) void kv_kernel() {
    const int bh = blockIdx.x;
    const int b = bh >> 4;
    const int h = bh & 15;
    const int lc = blockIdx.y;
    __shared__ float ks[32][64];
    __shared__ float vs[32][64];
    const int tid = threadIdx.x;
    const int tx = tid & 15;
    const int ty = tid >> 4;

    float acc[4][4];
#pragma unroll
    for (int i = 0; i < 4; i++)
#pragma unroll
        for (int j = 0; j < 4; j++) acc[i][j] = 0.0f;

    const size_t rowbase = (size_t)(b * LSEQ + lc * 256);
    for (int s = 0; s < 256; s += 32) {
#pragma unroll
        for (int i = 0; i < 2; i++) {
            int idx = tid + i * 256;
            int r = idx >> 4;
            int c = (idx & 15) * 4;
            size_t off = (rowbase + s + r) * EMB + h * HD + c;
            *(float4*)&ks[r][c] = *(const float4*)(g_k + off);
            *(float4*)&vs[r][c] = *(const float4*)(g_v + off);
        }
        __syncthreads();
#pragma unroll
        for (int l = 0; l < 32; l++) {
            float a[4], bb[4];
#pragma unroll
            for (int i = 0; i < 4; i++) a[i] = ks[l][ty * 4 + i];
#pragma unroll
            for (int j = 0; j < 4; j++) bb[j] = vs[l][tx * 4 + j];
#pragma unroll
            for (int i = 0; i < 4; i++)
#pragma unroll
                for (int j = 0; j < 4; j++) acc[i][j] += a[i] * bb[j];
        }
        __syncthreads();
    }

    float* kvp = g_kv + (size_t)bh * HD * HD;
#pragma unroll
    for (int i = 0; i < 4; i++)
#pragma unroll
        for (int j = 0; j < 4; j++)
            atomicAdd(kvp + (ty * 4 + i) * HD + tx * 4 + j, acc[i][j]);
}

// ---------------- out = q @ kv; SRMSNorm; * u; write fp16 y ----------------
__global__ __launch_bounds__(256) void outnorm_kernel() {
    const int bh = blockIdx.x;
    const int b = bh >> 4;
    const int h = bh & 15;
    const int lt = blockIdx.y;
    __shared__ float kvs[HD][HD];
    const int tid = threadIdx.x;

    for (int i = tid; i < HD * HD; i += 256)
        kvs[i >> 6][i & 63] = g_kv[(size_t)bh * HD * HD + i];
    __syncthreads();

    const int row = b * LSEQ + lt * 256 + tid;
    const float* qp = g_q + (size_t)row * EMB + h * HD;

    float qr[HD];
#pragma unroll
    for (int i = 0; i < 16; i++)
        *(float4*)&qr[i * 4] = *(const float4*)(qp + i * 4);

    float out[HD];
#pragma unroll
    for (int j = 0; j < HD; j++) out[j] = 0.0f;

#pragma unroll
    for (int kk = 0; kk < HD; kk++) {
        float qv = qr[kk];
#pragma unroll
        for (int j4 = 0; j4 < 16; j4++) {
            float4 kvv = *(const float4*)&kvs[kk][j4 * 4];
            out[j4 * 4 + 0] += qv * kvv.x;
            out[j4 * 4 + 1] += qv * kvv.y;
            out[j4 * 4 + 2] += qv * kvv.z;
            out[j4 * 4 + 3] += qv * kvv.w;
        }
    }

    float ss = 0.0f;
#pragma unroll
    for (int j = 0; j < HD; j++) ss += out[j] * out[j];
    float n = sqrtf(ss) * 0.125f;
    float inv = 1.0f / fmaxf(n, 1e-12f);

    const float* up = g_u + (size_t)row * EMB + h * HD;
#pragma unroll
    for (int i = 0; i < 16; i++) {
        float4 uv = *(const float4*)(up + i * 4);
        out[i * 4 + 0] *= inv * uv.x;
        out[i * 4 + 1] *= inv * uv.y;
        out[i * 4 + 2] *= inv * uv.z;
        out[i * 4 + 3] *= inv * uv.w;
    }

    // write fp16 y into tiled swizzled layout (ktile == h)
    int mt = row >> 7, r = row & 127;
    size_t base = ((size_t)(mt * KT + h)) * TILE_ELEMS;
#pragma unroll
    for (int ci = 0; ci < 8; ci++) {
        uint4 hh = conv8h(&out[ci * 8]);
        uint32_t off = swz(r * 128 + ci * 16);
        *(uint4*)((char*)g_yf + base * 2 + off) = hh;
    }
}

// ---------------------------------------------------------------------------
extern "C" void kernel_launch(void* const* d_in, const int* in_sizes, int n_in,
                              void* d_out, int out_size) {
    const float* x  = (const float*)d_in[0];
    const float* Wq = (const float*)d_in[1];
    const float* Wk = (const float*)d_in[2];
    const float* Wv = (const float*)d_in[3];
    const float* Wu = (const float*)d_in[4];
    const float* Wo = (const float*)d_in[5];
    float* out = (float*)d_out;

    cudaFuncSetAttribute(proj_mma, cudaFuncAttributeMaxDynamicSharedMemorySize, GSMEM);
    cudaFuncSetAttribute(fin_mma,  cudaFuncAttributeMaxDynamicSharedMemorySize, GSMEM);

    split_x_kernel<<<8192, 256>>>(x);
    split_w_kernel<<<2560, 256>>>(Wq, Wk, Wv, Wu, Wo);
    zero_kv_kernel<<<(NBH * HD * HD + 255) / 256, 256>>>();
    proj_mma<<<dim3(128, 8, 4), 256, GSMEM>>>();
    kv_kernel<<<dim3(NBH, LSEQ / 256), 256>>>();
    outnorm_kernel<<<dim3(NBH, LSEQ / 256), 256>>>();
    fin_mma<<<dim3(128, 8), 256, GSMEM>>>(out);
}

// round 8
// speedup vs baseline: 4.1825x; 1.1201x over previous
#include <cuda_runtime.h>
#include <cuda_fp16.h>
#include <math.h>
#include <stdint.h>

#define NROWS 16384      // b*l = 4*4096
#define EMB   1024
#define HD    64
#define NBH   64         // b*h
#define LSEQ  4096
#define KT    16         // K chunks of 64
#define TILE_ELEMS 8192  // 128 rows * 64 fp16
#define TILE_BYTES 16384
#define WSZ (8*16*8192)  // per-weight tiled elems (1024*1024)
#define STAGES 2
#define STAGE_BYTES (3*TILE_BYTES)   // A | Bh | Bl = 48KB
#define GSMEM (STAGES*STAGE_BYTES)   // 98304 -> 2 CTAs/SM

using f16 = __half;

// ---------------- scratch (device globals; allocation-free) ----------------
__device__ __align__(128) float g_q[NROWS * EMB];
__device__ __align__(128) float g_k[NROWS * EMB];
__device__ __align__(128) float g_v[NROWS * EMB];
__device__ __align__(128) float g_u[NROWS * EMB];
__device__ __align__(128) float g_kv[NBH * HD * HD];
__device__ __align__(128) f16   g_xf[NROWS * EMB];    // x, fp16 tiled
__device__ __align__(128) f16   g_yf[NROWS * EMB];    // y, fp16 tiled
__device__ __align__(128) f16   g_wh[5 * WSZ];        // W hi fp16 tiled
__device__ __align__(128) f16   g_wl[5 * WSZ];        // W lo fp16 tiled

// ---------------- helpers ----------------
__device__ __forceinline__ uint32_t s2u(const void* p) {
    uint32_t a;
    asm("{ .reg .u64 t; cvta.to.shared.u64 t, %1; cvt.u32.u64 %0, t; }" : "=r"(a) : "l"(p));
    return a;
}
__device__ __forceinline__ uint32_t swz(uint32_t off) { return off ^ ((off >> 3) & 0x70); }

__device__ __forceinline__ void cpa16(uint32_t saddr, const void* gaddr) {
    asm volatile("cp.async.cg.shared.global [%0], [%1], 16;" :: "r"(saddr), "l"(gaddr) : "memory");
}
__device__ __forceinline__ void cpa_commit() {
    asm volatile("cp.async.commit_group;" ::: "memory");
}
__device__ __forceinline__ void cpa_wait1() {
    asm volatile("cp.async.wait_group 1;" ::: "memory");
}
__device__ __forceinline__ void cpa_wait0() {
    asm volatile("cp.async.wait_group 0;" ::: "memory");
}
__device__ __forceinline__ void ldsm4(uint32_t& r0, uint32_t& r1, uint32_t& r2, uint32_t& r3,
                                      uint32_t addr) {
    asm volatile("ldmatrix.sync.aligned.m8n8.x4.shared.b16 {%0,%1,%2,%3}, [%4];"
                 : "=r"(r0), "=r"(r1), "=r"(r2), "=r"(r3) : "r"(addr));
}
__device__ __forceinline__ void mma16816(float* c, uint32_t a0, uint32_t a1, uint32_t a2,
                                         uint32_t a3, uint32_t b0, uint32_t b1) {
    asm volatile(
        "mma.sync.aligned.m16n8k16.row.col.f32.f16.f16.f32 "
        "{%0,%1,%2,%3},{%4,%5,%6,%7},{%8,%9},{%0,%1,%2,%3};"
        : "+f"(c[0]), "+f"(c[1]), "+f"(c[2]), "+f"(c[3])
        : "r"(a0), "r"(a1), "r"(a2), "r"(a3), "r"(b0), "r"(b1));
}

// pack 8 fp32 -> 8 fp16 (16B)
__device__ __forceinline__ uint4 conv8h(const float* v) {
    unsigned int u[4];
#pragma unroll
    for (int j = 0; j < 4; j++) {
        u[j] = (unsigned)__half_as_ushort(__float2half_rn(v[2 * j])) |
               ((unsigned)__half_as_ushort(__float2half_rn(v[2 * j + 1])) << 16);
    }
    return make_uint4(u[0], u[1], u[2], u[3]);
}
// split 8 fp32 -> hi/lo fp16 packed 16B each
__device__ __forceinline__ void split8h(const float* v, uint4& h, uint4& l) {
    unsigned int hu[4], lu[4];
#pragma unroll
    for (int j = 0; j < 4; j++) {
        float a = v[2 * j], b = v[2 * j + 1];
        f16 ah = __float2half_rn(a), bh = __float2half_rn(b);
        float ar = a - __half2float(ah), br = b - __half2float(bh);
        f16 al = __float2half_rn(ar), bl = __float2half_rn(br);
        hu[j] = (unsigned)__half_as_ushort(ah) | ((unsigned)__half_as_ushort(bh) << 16);
        lu[j] = (unsigned)__half_as_ushort(al) | ((unsigned)__half_as_ushort(bl) << 16);
    }
    h = make_uint4(hu[0], hu[1], hu[2], hu[3]);
    l = make_uint4(lu[0], lu[1], lu[2], lu[3]);
}

// ---------------- convert kernels (tiled SW128 layout) ----------------
__global__ __launch_bounds__(256) void split_x_kernel(const float* __restrict__ X) {
    int i = blockIdx.x * 256 + threadIdx.x;      // 0 .. 16384*128-1
    int row = i >> 7, c = i & 127;
    int kt = c >> 3, ci = c & 7;
    const float4* p = (const float4*)(X + (size_t)row * EMB + kt * 64 + ci * 8);
    float vv[8];
    *(float4*)&vv[0] = p[0];
    *(float4*)&vv[4] = p[1];
    uint4 h = conv8h(vv);
    int mt = row >> 7, r = row & 127;
    uint32_t off = swz(r * 128 + ci * 16);
    size_t base = ((size_t)(mt * KT + kt)) * TILE_ELEMS;
    *(uint4*)((char*)g_xf + base * 2 + off) = h;
}

__global__ __launch_bounds__(256) void split_w_kernel(const float* __restrict__ Wq,
                                                      const float* __restrict__ Wk,
                                                      const float* __restrict__ Wv,
                                                      const float* __restrict__ Wu,
                                                      const float* __restrict__ Wo) {
    int i = blockIdx.x * 256 + threadIdx.x;      // 0 .. 5120*128-1
    int row = i >> 7, c = i & 127;
    int widx = row >> 10, r = row & 1023;
    int kt = c >> 3, ci = c & 7;
    const float* W = (widx == 0) ? Wq : (widx == 1) ? Wk : (widx == 2) ? Wv : (widx == 3) ? Wu : Wo;
    const float4* p = (const float4*)(W + (size_t)r * EMB + kt * 64 + ci * 8);
    float vv[8];
    *(float4*)&vv[0] = p[0];
    *(float4*)&vv[4] = p[1];
    uint4 h, l;
    split8h(vv, h, l);
    int nt = r >> 7, rr = r & 127;
    uint32_t off = swz(rr * 128 + ci * 16);
    size_t base = (size_t)widx * WSZ + ((size_t)(nt * KT + kt)) * TILE_ELEMS;
    *(uint4*)((char*)g_wh + base * 2 + off) = h;
    *(uint4*)((char*)g_wl + base * 2 + off) = l;
}

// ---------------- mma.sync GEMM core: 128x128 CTA, BK=64, 2-stage ----------
// Stage layout: A(16K) Bh(16K) Bl(16K). 2 products: A*Bh + A*Bl.
// 2 CTAs/SM: cross-CTA overlap hides sync/wait bubbles.
__device__ __forceinline__ void gemm_mma(const f16* __restrict__ Ag,
                                         const f16* __restrict__ Bhg,
                                         const f16* __restrict__ Blg,
                                         float* __restrict__ C, int act) {
    extern __shared__ char sm[];
    uint32_t sb = s2u(sm);
    const int tid = threadIdx.x, lane = tid & 31, wid = tid >> 5;
    const int mt = blockIdx.x, nt = blockIdx.y;
    const int warpM = (wid >> 2) * 64;    // 0 / 64
    const int warpN = (wid & 3) * 32;     // 0,32,64,96

    auto load_stage = [&](int s, int kc) {
        uint32_t d = sb + s * STAGE_BYTES;
        size_t at = ((size_t)(mt * KT + kc)) * TILE_ELEMS;
        size_t bt = ((size_t)(nt * KT + kc)) * TILE_ELEMS;
        const char* srcs[3] = {(const char*)(Ag + at), (const char*)(Bhg + bt),
                               (const char*)(Blg + bt)};
#pragma unroll
        for (int blk = 0; blk < 3; blk++)
#pragma unroll
            for (int i = 0; i < 4; i++)
                cpa16(d + blk * TILE_BYTES + i * 4096 + tid * 16,
                      srcs[blk] + i * 4096 + tid * 16);
        cpa_commit();
    };

    float acc[4][4][4];
#pragma unroll
    for (int i = 0; i < 4; i++)
#pragma unroll
        for (int j = 0; j < 4; j++)
#pragma unroll
            for (int e = 0; e < 4; e++) acc[i][j][e] = 0.0f;

    const int aRow = warpM + (lane & 15);                       // + i*16
    const int aKg  = (lane >> 4);                               // + kk*2
    const int bRow = warpN + ((lane >> 4) << 3) + (lane & 7);   // + jj*16
    const int bKg  = ((lane >> 3) & 1);                         // + kk*2

    load_stage(0, 0);
    load_stage(1, 1);

    for (int kc = 0; kc < KT; kc++) {
        int cur = kc & 1;
        if (kc + 1 < KT) cpa_wait1(); else cpa_wait0();
        __syncthreads();

        uint32_t A  = sb + cur * STAGE_BYTES;
        uint32_t Bh = A + TILE_BYTES;
        uint32_t Bl = A + 2 * TILE_BYTES;

#pragma unroll
        for (int kk = 0; kk < 4; kk++) {
            uint32_t aX[4][4], bHf[4][2], bLf[4][2];
#pragma unroll
            for (int i = 0; i < 4; i++)
                ldsm4(aX[i][0], aX[i][1], aX[i][2], aX[i][3],
                      A + swz((aRow + i * 16) * 128 + (kk * 2 + aKg) * 16));
#pragma unroll
            for (int jj = 0; jj < 2; jj++) {
                uint32_t boff = swz((bRow + jj * 16) * 128 + (kk * 2 + bKg) * 16);
                ldsm4(bHf[2 * jj][0], bHf[2 * jj][1],
                      bHf[2 * jj + 1][0], bHf[2 * jj + 1][1], Bh + boff);
                ldsm4(bLf[2 * jj][0], bLf[2 * jj][1],
                      bLf[2 * jj + 1][0], bLf[2 * jj + 1][1], Bl + boff);
            }
#pragma unroll
            for (int i = 0; i < 4; i++)
#pragma unroll
                for (int j = 0; j < 4; j++)
                    mma16816(acc[i][j], aX[i][0], aX[i][1], aX[i][2], aX[i][3],
                             bHf[j][0], bHf[j][1]);
#pragma unroll
            for (int i = 0; i < 4; i++)
#pragma unroll
                for (int j = 0; j < 4; j++)
                    mma16816(acc[i][j], aX[i][0], aX[i][1], aX[i][2], aX[i][3],
                             bLf[j][0], bLf[j][1]);
        }
        __syncthreads();   // all warps done with 'cur' before it is reloaded
        if (kc + 2 < KT) load_stage(cur, kc + 2);
    }

    // epilogue
#pragma unroll
    for (int i = 0; i < 4; i++) {
#pragma unroll
        for (int j = 0; j < 4; j++) {
#pragma unroll
            for (int half = 0; half < 2; half++) {
                int row = mt * 128 + warpM + i * 16 + (lane >> 2) + half * 8;
                int col = nt * 128 + warpN + j * 8 + (lane & 3) * 2;
                float v0 = acc[i][j][half * 2 + 0];
                float v1 = acc[i][j][half * 2 + 1];
                if (act == 1) {
                    v0 = fmaxf(v0, 0.f) * 0.125f;
                    v1 = fmaxf(v1, 0.f) * 0.125f;
                } else if (act == 2) {
                    v0 = v0 / (1.f + expf(-v0));
                    v1 = v1 / (1.f + expf(-v1));
                }
                *(float2*)(C + (size_t)row * EMB + col) = make_float2(v0, v1);
            }
        }
    }
}

__global__ __launch_bounds__(256, 2) void proj_mma() {
    int z = blockIdx.z;
    float* C = (z == 0) ? g_q : (z == 1) ? g_k : (z == 2) ? g_v : g_u;
    int act  = (z <= 1) ? 1 : (z == 2) ? 0 : 2;
    gemm_mma(g_xf, g_wh + (size_t)z * WSZ, g_wl + (size_t)z * WSZ, C, act);
}

__global__ __launch_bounds__(256, 2) void fin_mma(float* __restrict__ out) {
    gemm_mma(g_yf, g_wh + (size_t)4 * WSZ, g_wl + (size_t)4 * WSZ, out, 0);
}

// ---------------- kv accumulation ----------------
__global__ void zero_kv_kernel() {
    int i = blockIdx.x * 256 + threadIdx.x;
    if (i < NBH * HD * HD) g_kv[i] = 0.0f;
}

__global__ __launch_bounds__(256) void kv_kernel() {
    const int bh = blockIdx.x;
    const int b = bh >> 4;
    const int h = bh & 15;
    const int lc = blockIdx.y;
    __shared__ float ks[32][64];
    __shared__ float vs[32][64];
    const int tid = threadIdx.x;
    const int tx = tid & 15;
    const int ty = tid >> 4;

    float acc[4][4];
#pragma unroll
    for (int i = 0; i < 4; i++)
#pragma unroll
        for (int j = 0; j < 4; j++) acc[i][j] = 0.0f;

    const size_t rowbase = (size_t)(b * LSEQ + lc * 256);
    for (int s = 0; s < 256; s += 32) {
#pragma unroll
        for (int i = 0; i < 2; i++) {
            int idx = tid + i * 256;
            int r = idx >> 4;
            int c = (idx & 15) * 4;
            size_t off = (rowbase + s + r) * EMB + h * HD + c;
            *(float4*)&ks[r][c] = *(const float4*)(g_k + off);
            *(float4*)&vs[r][c] = *(const float4*)(g_v + off);
        }
        __syncthreads();
#pragma unroll
        for (int l = 0; l < 32; l++) {
            float a[4], bb[4];
#pragma unroll
            for (int i = 0; i < 4; i++) a[i] = ks[l][ty * 4 + i];
#pragma unroll
            for (int j = 0; j < 4; j++) bb[j] = vs[l][tx * 4 + j];
#pragma unroll
            for (int i = 0; i < 4; i++)
#pragma unroll
                for (int j = 0; j < 4; j++) acc[i][j] += a[i] * bb[j];
        }
        __syncthreads();
    }

    float* kvp = g_kv + (size_t)bh * HD * HD;
#pragma unroll
    for (int i = 0; i < 4; i++)
#pragma unroll
        for (int j = 0; j < 4; j++)
            atomicAdd(kvp + (ty * 4 + i) * HD + tx * 4 + j, acc[i][j]);
}

// ---------------- out = q @ kv; SRMSNorm; * u; write fp16 y ----------------
__global__ __launch_bounds__(256) void outnorm_kernel() {
    const int bh = blockIdx.x;
    const int b = bh >> 4;
    const int h = bh & 15;
    const int lt = blockIdx.y;
    __shared__ float kvs[HD][HD];
    const int tid = threadIdx.x;

    for (int i = tid; i < HD * HD; i += 256)
        kvs[i >> 6][i & 63] = g_kv[(size_t)bh * HD * HD + i];
    __syncthreads();

    const int row = b * LSEQ + lt * 256 + tid;
    const float* qp = g_q + (size_t)row * EMB + h * HD;

    float qr[HD];
#pragma unroll
    for (int i = 0; i < 16; i++)
        *(float4*)&qr[i * 4] = *(const float4*)(qp + i * 4);

    float out[HD];
#pragma unroll
    for (int j = 0; j < HD; j++) out[j] = 0.0f;

#pragma unroll
    for (int kk = 0; kk < HD; kk++) {
        float qv = qr[kk];
#pragma unroll
        for (int j4 = 0; j4 < 16; j4++) {
            float4 kvv = *(const float4*)&kvs[kk][j4 * 4];
            out[j4 * 4 + 0] += qv * kvv.x;
            out[j4 * 4 + 1] += qv * kvv.y;
            out[j4 * 4 + 2] += qv * kvv.z;
            out[j4 * 4 + 3] += qv * kvv.w;
        }
    }

    float ss = 0.0f;
#pragma unroll
    for (int j = 0; j < HD; j++) ss += out[j] * out[j];
    float n = sqrtf(ss) * 0.125f;
    float inv = 1.0f / fmaxf(n, 1e-12f);

    const float* up = g_u + (size_t)row * EMB + h * HD;
#pragma unroll
    for (int i = 0; i < 16; i++) {
        float4 uv = *(const float4*)(up + i * 4);
        out[i * 4 + 0] *= inv * uv.x;
        out[i * 4 + 1] *= inv * uv.y;
        out[i * 4 + 2] *= inv * uv.z;
        out[i * 4 + 3] *= inv * uv.w;
    }

    // write fp16 y into tiled swizzled layout (ktile == h)
    int mt = row >> 7, r = row & 127;
    size_t base = ((size_t)(mt * KT + h)) * TILE_ELEMS;
#pragma unroll
    for (int ci = 0; ci < 8; ci++) {
        uint4 hh = conv8h(&out[ci * 8]);
        uint32_t off = swz(r * 128 + ci * 16);
        *(uint4*)((char*)g_yf + base * 2 + off) = hh;
    }
}

// ---------------------------------------------------------------------------
extern "C" void kernel_launch(void* const* d_in, const int* in_sizes, int n_in,
                              void* d_out, int out_size) {
    const float* x  = (const float*)d_in[0];
    const float* Wq = (const float*)d_in[1];
    const float* Wk = (const float*)d_in[2];
    const float* Wv = (const float*)d_in[3];
    const float* Wu = (const float*)d_in[4];
    const float* Wo = (const float*)d_in[5];
    float* out = (float*)d_out;

    cudaFuncSetAttribute(proj_mma, cudaFuncAttributeMaxDynamicSharedMemorySize, GSMEM);
    cudaFuncSetAttribute(fin_mma,  cudaFuncAttributeMaxDynamicSharedMemorySize, GSMEM);

    split_x_kernel<<<8192, 256>>>(x);
    split_w_kernel<<<2560, 256>>>(Wq, Wk, Wv, Wu, Wo);
    zero_kv_kernel<<<(NBH * HD * HD + 255) / 256, 256>>>();
    proj_mma<<<dim3(128, 8, 4), 256, GSMEM>>>();
    kv_kernel<<<dim3(NBH, LSEQ / 256), 256>>>();
    outnorm_kernel<<<dim3(NBH, LSEQ / 256), 256>>>();
    fin_mma<<<dim3(128, 8), 256, GSMEM>>>(out);
}

// round 9
// speedup vs baseline: 4.4825x; 1.0717x over previous
#include <cuda_runtime.h>
#include <cuda_fp16.h>
#include <math.h>
#include <stdint.h>

#define NROWS 16384      // b*l = 4*4096
#define EMB   1024
#define HD    64
#define NBH   64         // b*h
#define LSEQ  4096
#define KT    16         // K chunks of 64
#define TILE_ELEMS 8192  // 128 rows * 64 fp16
#define TILE_BYTES 16384
#define WSZ (8*16*8192)  // per-weight tiled elems (1024*1024)
#define STAGES 2
#define STAGE_BYTES (3*TILE_BYTES)   // A | Bh | Bl = 48KB
#define GSMEM (STAGES*STAGE_BYTES)   // 98304 -> 2 CTAs/SM

using f16 = __half;

// ---------------- scratch (device globals; allocation-free) ----------------
__device__ __align__(128) f16   g_xf[NROWS * EMB];    // x fp16 tiled
__device__ __align__(128) f16   g_yf[NROWS * EMB];    // y fp16 tiled
__device__ __align__(128) f16   g_wh[5 * WSZ];        // W hi fp16 tiled
__device__ __align__(128) f16   g_wl[5 * WSZ];        // W lo fp16 tiled
__device__ __align__(128) f16   g_qh[NROWS * EMB];    // q hi, head-tiled
__device__ __align__(128) f16   g_ql[NROWS * EMB];    // q lo
__device__ __align__(128) float g_uF[NROWS * EMB];    // u fp32, head-tiled
__device__ __align__(128) f16   g_kTh[NROWS * EMB];   // k^T hi  [bh][lc][a64][l64]
__device__ __align__(128) f16   g_kTl[NROWS * EMB];
__device__ __align__(128) f16   g_vTh[NROWS * EMB];   // v^T hi
__device__ __align__(128) f16   g_vTl[NROWS * EMB];
__device__ __align__(128) float g_kvT[NBH * HD * HD]; // kv^T fp32 accum
__device__ __align__(128) f16   g_kvh[NBH * HD * HD]; // kv^T hi tiles
__device__ __align__(128) f16   g_kvl[NBH * HD * HD];

// ---------------- helpers ----------------
__device__ __forceinline__ uint32_t s2u(const void* p) {
    uint32_t a;
    asm("{ .reg .u64 t; cvta.to.shared.u64 t, %1; cvt.u32.u64 %0, t; }" : "=r"(a) : "l"(p));
    return a;
}
__device__ __forceinline__ uint32_t swz(uint32_t off) { return off ^ ((off >> 3) & 0x70); }

__device__ __forceinline__ void cpa16(uint32_t saddr, const void* gaddr) {
    asm volatile("cp.async.cg.shared.global [%0], [%1], 16;" :: "r"(saddr), "l"(gaddr) : "memory");
}
__device__ __forceinline__ void cpa_commit() {
    asm volatile("cp.async.commit_group;" ::: "memory");
}
__device__ __forceinline__ void cpa_wait1() {
    asm volatile("cp.async.wait_group 1;" ::: "memory");
}
__device__ __forceinline__ void cpa_wait0() {
    asm volatile("cp.async.wait_group 0;" ::: "memory");
}
__device__ __forceinline__ void ldsm4(uint32_t& r0, uint32_t& r1, uint32_t& r2, uint32_t& r3,
                                      uint32_t addr) {
    asm volatile("ldmatrix.sync.aligned.m8n8.x4.shared.b16 {%0,%1,%2,%3}, [%4];"
                 : "=r"(r0), "=r"(r1), "=r"(r2), "=r"(r3) : "r"(addr));
}
__device__ __forceinline__ void mma16816(float* c, uint32_t a0, uint32_t a1, uint32_t a2,
                                         uint32_t a3, uint32_t b0, uint32_t b1) {
    asm volatile(
        "mma.sync.aligned.m16n8k16.row.col.f32.f16.f16.f32 "
        "{%0,%1,%2,%3},{%4,%5,%6,%7},{%8,%9},{%0,%1,%2,%3};"
        : "+f"(c[0]), "+f"(c[1]), "+f"(c[2]), "+f"(c[3])
        : "r"(a0), "r"(a1), "r"(a2), "r"(a3), "r"(b0), "r"(b1));
}

__device__ __forceinline__ uint4 conv8h(const float* v) {
    unsigned int u[4];
#pragma unroll
    for (int j = 0; j < 4; j++) {
        u[j] = (unsigned)__half_as_ushort(__float2half_rn(v[2 * j])) |
               ((unsigned)__half_as_ushort(__float2half_rn(v[2 * j + 1])) << 16);
    }
    return make_uint4(u[0], u[1], u[2], u[3]);
}
__device__ __forceinline__ void split8h(const float* v, uint4& h, uint4& l) {
    unsigned int hu[4], lu[4];
#pragma unroll
    for (int j = 0; j < 4; j++) {
        float a = v[2 * j], b = v[2 * j + 1];
        f16 ah = __float2half_rn(a), bh = __float2half_rn(b);
        float ar = a - __half2float(ah), br = b - __half2float(bh);
        f16 al = __float2half_rn(ar), bl = __float2half_rn(br);
        hu[j] = (unsigned)__half_as_ushort(ah) | ((unsigned)__half_as_ushort(bh) << 16);
        lu[j] = (unsigned)__half_as_ushort(al) | ((unsigned)__half_as_ushort(bl) << 16);
    }
    h = make_uint4(hu[0], hu[1], hu[2], hu[3]);
    l = make_uint4(lu[0], lu[1], lu[2], lu[3]);
}
__device__ __forceinline__ void split2h(float v0, float v1, uint32_t& hv, uint32_t& lv) {
    f16 h0 = __float2half_rn(v0), h1 = __float2half_rn(v1);
    f16 l0 = __float2half_rn(v0 - __half2float(h0));
    f16 l1 = __float2half_rn(v1 - __half2float(h1));
    hv = (unsigned)__half_as_ushort(h0) | ((unsigned)__half_as_ushort(h1) << 16);
    lv = (unsigned)__half_as_ushort(l0) | ((unsigned)__half_as_ushort(l1) << 16);
}

// ---------------- convert kernels ----------------
__global__ __launch_bounds__(256) void split_x_kernel(const float* __restrict__ X) {
    int i = blockIdx.x * 256 + threadIdx.x;
    int row = i >> 7, c = i & 127;
    int kt = c >> 3, ci = c & 7;
    const float4* p = (const float4*)(X + (size_t)row * EMB + kt * 64 + ci * 8);
    float vv[8];
    *(float4*)&vv[0] = p[0];
    *(float4*)&vv[4] = p[1];
    uint4 h = conv8h(vv);
    int mt = row >> 7, r = row & 127;
    uint32_t off = swz(r * 128 + ci * 16);
    size_t base = ((size_t)(mt * KT + kt)) * TILE_ELEMS;
    *(uint4*)((char*)g_xf + base * 2 + off) = h;
}

__global__ __launch_bounds__(256) void split_w_kernel(const float* __restrict__ Wq,
                                                      const float* __restrict__ Wk,
                                                      const float* __restrict__ Wv,
                                                      const float* __restrict__ Wu,
                                                      const float* __restrict__ Wo) {
    int i = blockIdx.x * 256 + threadIdx.x;
    int row = i >> 7, c = i & 127;
    int widx = row >> 10, r = row & 1023;
    int kt = c >> 3, ci = c & 7;
    const float* W = (widx == 0) ? Wq : (widx == 1) ? Wk : (widx == 2) ? Wv : (widx == 3) ? Wu : Wo;
    const float4* p = (const float4*)(W + (size_t)r * EMB + kt * 64 + ci * 8);
    float vv[8];
    *(float4*)&vv[0] = p[0];
    *(float4*)&vv[4] = p[1];
    uint4 h, l;
    split8h(vv, h, l);
    int nt = r >> 7, rr = r & 127;
    uint32_t off = swz(rr * 128 + ci * 16);
    size_t base = (size_t)widx * WSZ + ((size_t)(nt * KT + kt)) * TILE_ELEMS;
    *(uint4*)((char*)g_wh + base * 2 + off) = h;
    *(uint4*)((char*)g_wl + base * 2 + off) = l;
}

__global__ void zero_kv_kernel() {
    int i = blockIdx.x * 256 + threadIdx.x;
    if (i < NBH * HD * HD) g_kvT[i] = 0.0f;
}

// ---------------- proj GEMM: 128x128 CTA, BK=64, 2-stage, fused epilogues --
__global__ __launch_bounds__(256, 2) void proj_mma() {
    extern __shared__ char sm[];
    uint32_t sb = s2u(sm);
    const int tid = threadIdx.x, lane = tid & 31, wid = tid >> 5;
    const int mt = blockIdx.x, nt = blockIdx.y, z = blockIdx.z;
    const int warpM = (wid >> 2) * 64;
    const int warpN = (wid & 3) * 32;
    const f16* Bhg = g_wh + (size_t)z * WSZ;
    const f16* Blg = g_wl + (size_t)z * WSZ;

    auto load_stage = [&](int s, int kc) {
        uint32_t d = sb + s * STAGE_BYTES;
        size_t at = ((size_t)(mt * KT + kc)) * TILE_ELEMS;
        size_t bt = ((size_t)(nt * KT + kc)) * TILE_ELEMS;
        const char* srcs[3] = {(const char*)(g_xf + at), (const char*)(Bhg + bt),
                               (const char*)(Blg + bt)};
#pragma unroll
        for (int blk = 0; blk < 3; blk++)
#pragma unroll
            for (int i = 0; i < 4; i++)
                cpa16(d + blk * TILE_BYTES + i * 4096 + tid * 16,
                      srcs[blk] + i * 4096 + tid * 16);
        cpa_commit();
    };

    float acc[4][4][4];
#pragma unroll
    for (int i = 0; i < 4; i++)
#pragma unroll
        for (int j = 0; j < 4; j++)
#pragma unroll
            for (int e = 0; e < 4; e++) acc[i][j][e] = 0.0f;

    const int aRow = warpM + (lane & 15);
    const int aKg  = (lane >> 4);
    const int bRow = warpN + ((lane >> 4) << 3) + (lane & 7);
    const int bKg  = ((lane >> 3) & 1);

    load_stage(0, 0);
    load_stage(1, 1);

    for (int kc = 0; kc < KT; kc++) {
        int cur = kc & 1;
        if (kc + 1 < KT) cpa_wait1(); else cpa_wait0();
        __syncthreads();

        uint32_t A  = sb + cur * STAGE_BYTES;
        uint32_t Bh = A + TILE_BYTES;
        uint32_t Bl = A + 2 * TILE_BYTES;

#pragma unroll
        for (int kk = 0; kk < 4; kk++) {
            uint32_t aX[4][4], bHf[4][2], bLf[4][2];
#pragma unroll
            for (int i = 0; i < 4; i++)
                ldsm4(aX[i][0], aX[i][1], aX[i][2], aX[i][3],
                      A + swz((aRow + i * 16) * 128 + (kk * 2 + aKg) * 16));
#pragma unroll
            for (int jj = 0; jj < 2; jj++) {
                uint32_t boff = swz((bRow + jj * 16) * 128 + (kk * 2 + bKg) * 16);
                ldsm4(bHf[2 * jj][0], bHf[2 * jj][1],
                      bHf[2 * jj + 1][0], bHf[2 * jj + 1][1], Bh + boff);
                ldsm4(bLf[2 * jj][0], bLf[2 * jj][1],
                      bLf[2 * jj + 1][0], bLf[2 * jj + 1][1], Bl + boff);
            }
#pragma unroll
            for (int i = 0; i < 4; i++)
#pragma unroll
                for (int j = 0; j < 4; j++)
                    mma16816(acc[i][j], aX[i][0], aX[i][1], aX[i][2], aX[i][3],
                             bHf[j][0], bHf[j][1]);
#pragma unroll
            for (int i = 0; i < 4; i++)
#pragma unroll
                for (int j = 0; j < 4; j++)
                    mma16816(acc[i][j], aX[i][0], aX[i][1], aX[i][2], aX[i][3],
                             bLf[j][0], bLf[j][1]);
        }
        __syncthreads();
        if (kc + 2 < KT) load_stage(cur, kc + 2);
    }

    // ---- epilogues ----
    if (z == 0 || z == 3) {
        // q: relu*0.125, split hi/lo fp16 head-tiles.  u: silu, fp32 head-tiles.
#pragma unroll
        for (int i = 0; i < 4; i++) {
#pragma unroll
            for (int j = 0; j < 4; j++) {
#pragma unroll
                for (int half = 0; half < 2; half++) {
                    int r = warpM + i * 16 + (lane >> 2) + half * 8;
                    int c = warpN + j * 8 + (lane & 3) * 2;
                    int h = c >> 6, cin = c & 63;
                    float v0 = acc[i][j][half * 2 + 0];
                    float v1 = acc[i][j][half * 2 + 1];
                    size_t tile = (size_t)mt * 16 + (nt * 2 + h);
                    if (z == 0) {
                        v0 = fmaxf(v0, 0.f) * 0.125f;
                        v1 = fmaxf(v1, 0.f) * 0.125f;
                        uint32_t hv, lv;
                        split2h(v0, v1, hv, lv);
                        size_t base = tile * TILE_ELEMS * 2;
                        uint32_t off = swz(r * 128 + cin * 2);
                        *(uint32_t*)((char*)g_qh + base + off) = hv;
                        *(uint32_t*)((char*)g_ql + base + off) = lv;
                    } else {
                        v0 = v0 / (1.f + expf(-v0));
                        v1 = v1 / (1.f + expf(-v1));
                        *(float2*)(g_uF + tile * TILE_ELEMS + r * 64 + cin) =
                            make_float2(v0, v1);
                    }
                }
            }
        }
    } else {
        // k (z=1): relu*0.125;  v (z=2): identity. Transpose via smem, split hi/lo.
        float* smf = (float*)sm;   // 128 x 130 fp32 stage (66.5KB < 96KB)
#pragma unroll
        for (int i = 0; i < 4; i++) {
#pragma unroll
            for (int j = 0; j < 4; j++) {
#pragma unroll
                for (int half = 0; half < 2; half++) {
                    int r = warpM + i * 16 + (lane >> 2) + half * 8;
                    int c = warpN + j * 8 + (lane & 3) * 2;
                    float v0 = acc[i][j][half * 2 + 0];
                    float v1 = acc[i][j][half * 2 + 1];
                    if (z == 1) {
                        v0 = fmaxf(v0, 0.f) * 0.125f;
                        v1 = fmaxf(v1, 0.f) * 0.125f;
                    }
                    *(float2*)&smf[r * 130 + c] = make_float2(v0, v1);
                }
            }
        }
        __syncthreads();
        int a = tid & 63, hl = (tid >> 6) & 1, lcl = tid >> 7;
        float vv[64];
#pragma unroll
        for (int l = 0; l < 64; l++)
            vv[l] = smf[(lcl * 64 + l) * 130 + hl * 64 + a];
        int b = mt >> 5;
        int bh = b * 16 + nt * 2 + hl;
        int lc = (mt & 31) * 2 + lcl;
        size_t base = (((size_t)bh * 64 + lc) * 4096) * 2;
        f16* dh = (z == 1) ? g_kTh : g_vTh;
        f16* dl = (z == 1) ? g_kTl : g_vTl;
#pragma unroll
        for (int g = 0; g < 8; g++) {
            uint4 hq, lq;
            split8h(&vv[g * 8], hq, lq);
            uint32_t off = swz(a * 128 + g * 16);
            *(uint4*)((char*)dh + base + off) = hq;
            *(uint4*)((char*)dl + base + off) = lq;
        }
    }
}

// ---------------- fin GEMM (unchanged structure) ----------------
__global__ __launch_bounds__(256, 2) void fin_mma(float* __restrict__ C) {
    extern __shared__ char sm[];
    uint32_t sb = s2u(sm);
    const int tid = threadIdx.x, lane = tid & 31, wid = tid >> 5;
    const int mt = blockIdx.x, nt = blockIdx.y;
    const int warpM = (wid >> 2) * 64;
    const int warpN = (wid & 3) * 32;
    const f16* Bhg = g_wh + (size_t)4 * WSZ;
    const f16* Blg = g_wl + (size_t)4 * WSZ;

    auto load_stage = [&](int s, int kc) {
        uint32_t d = sb + s * STAGE_BYTES;
        size_t at = ((size_t)(mt * KT + kc)) * TILE_ELEMS;
        size_t bt = ((size_t)(nt * KT + kc)) * TILE_ELEMS;
        const char* srcs[3] = {(const char*)(g_yf + at), (const char*)(Bhg + bt),
                               (const char*)(Blg + bt)};
#pragma unroll
        for (int blk = 0; blk < 3; blk++)
#pragma unroll
            for (int i = 0; i < 4; i++)
                cpa16(d + blk * TILE_BYTES + i * 4096 + tid * 16,
                      srcs[blk] + i * 4096 + tid * 16);
        cpa_commit();
    };

    float acc[4][4][4];
#pragma unroll
    for (int i = 0; i < 4; i++)
#pragma unroll
        for (int j = 0; j < 4; j++)
#pragma unroll
            for (int e = 0; e < 4; e++) acc[i][j][e] = 0.0f;

    const int aRow = warpM + (lane & 15);
    const int aKg  = (lane >> 4);
    const int bRow = warpN + ((lane >> 4) << 3) + (lane & 7);
    const int bKg  = ((lane >> 3) & 1);

    load_stage(0, 0);
    load_stage(1, 1);

    for (int kc = 0; kc < KT; kc++) {
        int cur = kc & 1;
        if (kc + 1 < KT) cpa_wait1(); else cpa_wait0();
        __syncthreads();

        uint32_t A  = sb + cur * STAGE_BYTES;
        uint32_t Bh = A + TILE_BYTES;
        uint32_t Bl = A + 2 * TILE_BYTES;

#pragma unroll
        for (int kk = 0; kk < 4; kk++) {
            uint32_t aX[4][4], bHf[4][2], bLf[4][2];
#pragma unroll
            for (int i = 0; i < 4; i++)
                ldsm4(aX[i][0], aX[i][1], aX[i][2], aX[i][3],
                      A + swz((aRow + i * 16) * 128 + (kk * 2 + aKg) * 16));
#pragma unroll
            for (int jj = 0; jj < 2; jj++) {
                uint32_t boff = swz((bRow + jj * 16) * 128 + (kk * 2 + bKg) * 16);
                ldsm4(bHf[2 * jj][0], bHf[2 * jj][1],
                      bHf[2 * jj + 1][0], bHf[2 * jj + 1][1], Bh + boff);
                ldsm4(bLf[2 * jj][0], bLf[2 * jj][1],
                      bLf[2 * jj + 1][0], bLf[2 * jj + 1][1], Bl + boff);
            }
#pragma unroll
            for (int i = 0; i < 4; i++)
#pragma unroll
                for (int j = 0; j < 4; j++)
                    mma16816(acc[i][j], aX[i][0], aX[i][1], aX[i][2], aX[i][3],
                             bHf[j][0], bHf[j][1]);
#pragma unroll
            for (int i = 0; i < 4; i++)
#pragma unroll
                for (int j = 0; j < 4; j++)
                    mma16816(acc[i][j], aX[i][0], aX[i][1], aX[i][2], aX[i][3],
                             bLf[j][0], bLf[j][1]);
        }
        __syncthreads();
        if (kc + 2 < KT) load_stage(cur, kc + 2);
    }

#pragma unroll
    for (int i = 0; i < 4; i++)
#pragma unroll
        for (int j = 0; j < 4; j++)
#pragma unroll
            for (int half = 0; half < 2; half++) {
                int row = mt * 128 + warpM + i * 16 + (lane >> 2) + half * 8;
                int col = nt * 128 + warpN + j * 8 + (lane & 3) * 2;
                *(float2*)(C + (size_t)row * EMB + col) =
                    make_float2(acc[i][j][half * 2], acc[i][j][half * 2 + 1]);
            }
}

// ---------------- kv via mma: kvT[b][a] += sum_l v[l,b]*k[l,a] ----------------
__global__ __launch_bounds__(128, 3) void kv_mma() {
    extern __shared__ char sm[];
    uint32_t sb = s2u(sm);
    const int tid = threadIdx.x, lane = tid & 31, wid = tid >> 5;
    const int bh = blockIdx.x, split = blockIdx.y;
    const int warpM = (wid >> 1) * 32;
    const int warpN = (wid & 1) * 32;

    auto load_stage = [&](int s, int ch) {
        int lc = split * 8 + ch;
        size_t tb = (((size_t)bh * 64 + lc) * 4096) * 2;   // tile byte offset
        const char* srcs[4] = {(const char*)g_vTh + tb, (const char*)g_vTl + tb,
                               (const char*)g_kTh + tb, (const char*)g_kTl + tb};
        uint32_t d = sb + s * 32768;
#pragma unroll
        for (int blk = 0; blk < 4; blk++)
#pragma unroll
            for (int i = 0; i < 4; i++)
                cpa16(d + blk * 8192 + i * 2048 + tid * 16,
                      srcs[blk] + i * 2048 + tid * 16);
        cpa_commit();
    };

    float acc[2][4][4];
#pragma unroll
    for (int i = 0; i < 2; i++)
#pragma unroll
        for (int j = 0; j < 4; j++)
#pragma unroll
            for (int e = 0; e < 4; e++) acc[i][j][e] = 0.0f;

    const int aRow = warpM + (lane & 15);
    const int aKg  = (lane >> 4);
    const int bRow = warpN + ((lane >> 4) << 3) + (lane & 7);
    const int bKg  = ((lane >> 3) & 1);

    load_stage(0, 0);
    load_stage(1, 1);

    for (int ch = 0; ch < 8; ch++) {
        int cur = ch & 1;
        if (ch + 1 < 8) cpa_wait1(); else cpa_wait0();
        __syncthreads();
        uint32_t Avh = sb + cur * 32768;
        uint32_t Avl = Avh + 8192, Bkh = Avh + 16384, Bkl = Avh + 24576;

#pragma unroll
        for (int kk = 0; kk < 4; kk++) {
            uint32_t avh[2][4], avl[2][4], bkh[4][2], bkl[4][2];
#pragma unroll
            for (int i = 0; i < 2; i++) {
                uint32_t aoff = swz((aRow + i * 16) * 128 + (kk * 2 + aKg) * 16);
                ldsm4(avh[i][0], avh[i][1], avh[i][2], avh[i][3], Avh + aoff);
                ldsm4(avl[i][0], avl[i][1], avl[i][2], avl[i][3], Avl + aoff);
            }
#pragma unroll
            for (int jj = 0; jj < 2; jj++) {
                uint32_t boff = swz((bRow + jj * 16) * 128 + (kk * 2 + bKg) * 16);
                ldsm4(bkh[2 * jj][0], bkh[2 * jj][1],
                      bkh[2 * jj + 1][0], bkh[2 * jj + 1][1], Bkh + boff);
                ldsm4(bkl[2 * jj][0], bkl[2 * jj][1],
                      bkl[2 * jj + 1][0], bkl[2 * jj + 1][1], Bkl + boff);
            }
#pragma unroll
            for (int i = 0; i < 2; i++)
#pragma unroll
                for (int j = 0; j < 4; j++) {
                    mma16816(acc[i][j], avh[i][0], avh[i][1], avh[i][2], avh[i][3],
                             bkh[j][0], bkh[j][1]);
                    mma16816(acc[i][j], avh[i][0], avh[i][1], avh[i][2], avh[i][3],
                             bkl[j][0], bkl[j][1]);
                    mma16816(acc[i][j], avl[i][0], avl[i][1], avl[i][2], avl[i][3],
                             bkh[j][0], bkh[j][1]);
                }
        }
        __syncthreads();
        if (ch + 2 < 8) load_stage(cur, ch + 2);
    }

    float* kvp = g_kvT + (size_t)bh * 4096;
#pragma unroll
    for (int i = 0; i < 2; i++)
#pragma unroll
        for (int j = 0; j < 4; j++)
#pragma unroll
            for (int half = 0; half < 2; half++) {
                int row = warpM + i * 16 + (lane >> 2) + half * 8;
                int col = warpN + j * 8 + (lane & 3) * 2;
                atomicAdd(kvp + row * 64 + col,     acc[i][j][half * 2]);
                atomicAdd(kvp + row * 64 + col + 1, acc[i][j][half * 2 + 1]);
            }
}

// ---------------- kvT fp32 -> hi/lo fp16 swizzled tiles ----------------
__global__ __launch_bounds__(256) void kv_split() {
    int bh = blockIdx.x, t = threadIdx.x;
    int row = t >> 2, c0 = (t & 3) * 16;
    const float* src = g_kvT + (size_t)bh * 4096 + row * 64 + c0;
    float vv[16];
#pragma unroll
    for (int g = 0; g < 4; g++) *(float4*)&vv[g * 4] = ((const float4*)src)[g];
    size_t base = ((size_t)bh * 4096) * 2;
#pragma unroll
    for (int g = 0; g < 2; g++) {
        uint4 hq, lq;
        split8h(&vv[g * 8], hq, lq);
        uint32_t off = swz(row * 128 + c0 * 2 + g * 16);
        *(uint4*)((char*)g_kvh + base + off) = hq;
        *(uint4*)((char*)g_kvl + base + off) = lq;
    }
}

// ---------------- out = q@kv; SRMSNorm; *u; write fp16 y tiles ----------------
__global__ __launch_bounds__(256) void out_mma() {
    extern __shared__ char sm[];
    uint32_t sb = s2u(sm);
    const int tid = threadIdx.x, lane = tid & 31, wid = tid >> 5;
    const int mt = blockIdx.x, h = blockIdx.y;
    const int bh = (mt >> 5) * 16 + h;
    const size_t qbase = ((size_t)mt * 16 + h) * TILE_ELEMS * 2;    // bytes
    const size_t kvbase = ((size_t)bh * 4096) * 2;

    // single-shot loads: qh(16K) ql(16K) kvh(8K) kvl(8K)
#pragma unroll
    for (int i = 0; i < 4; i++) {
        cpa16(sb + i * 4096 + tid * 16, (const char*)g_qh + qbase + i * 4096 + tid * 16);
        cpa16(sb + 16384 + i * 4096 + tid * 16,
              (const char*)g_ql + qbase + i * 4096 + tid * 16);
    }
#pragma unroll
    for (int i = 0; i < 2; i++) {
        cpa16(sb + 32768 + i * 4096 + tid * 16,
              (const char*)g_kvh + kvbase + i * 4096 + tid * 16);
        cpa16(sb + 40960 + i * 4096 + tid * 16,
              (const char*)g_kvl + kvbase + i * 4096 + tid * 16);
    }
    cpa_commit();
    cpa_wait0();
    __syncthreads();

    const int warpM = wid * 16;
    const int aRow = warpM + (lane & 15);
    const int aKg  = (lane >> 4);
    const int bRow = ((lane >> 4) << 3) + (lane & 7);
    const int bKg  = ((lane >> 3) & 1);
    const uint32_t Qh = sb, Ql = sb + 16384, Kh = sb + 32768, Kl = sb + 40960;

    float acc[8][4];
#pragma unroll
    for (int j = 0; j < 8; j++)
#pragma unroll
        for (int e = 0; e < 4; e++) acc[j][e] = 0.0f;

#pragma unroll
    for (int kk = 0; kk < 4; kk++) {
        uint32_t aqh[4], aql[4], bvh[8][2], bvl[8][2];
        uint32_t aoff = swz(aRow * 128 + (kk * 2 + aKg) * 16);
        ldsm4(aqh[0], aqh[1], aqh[2], aqh[3], Qh + aoff);
        ldsm4(aql[0], aql[1], aql[2], aql[3], Ql + aoff);
#pragma unroll
        for (int jj = 0; jj < 4; jj++) {
            uint32_t boff = swz((jj * 16 + bRow) * 128 + (kk * 2 + bKg) * 16);
            ldsm4(bvh[2 * jj][0], bvh[2 * jj][1],
                  bvh[2 * jj + 1][0], bvh[2 * jj + 1][1], Kh + boff);
            ldsm4(bvl[2 * jj][0], bvl[2 * jj][1],
                  bvl[2 * jj + 1][0], bvl[2 * jj + 1][1], Kl + boff);
        }
#pragma unroll
        for (int j = 0; j < 8; j++) {
            mma16816(acc[j], aqh[0], aqh[1], aqh[2], aqh[3], bvh[j][0], bvh[j][1]);
            mma16816(acc[j], aqh[0], aqh[1], aqh[2], aqh[3], bvl[j][0], bvl[j][1]);
            mma16816(acc[j], aql[0], aql[1], aql[2], aql[3], bvh[j][0], bvh[j][1]);
        }
    }

    // row-wise SRMSNorm + u-multiply + fp16 tiled y store
    const size_t ub = ((size_t)mt * 16 + h) * TILE_ELEMS;           // fp32 elems
    const size_t yb = ((size_t)mt * 16 + h) * TILE_ELEMS * 2;       // bytes
#pragma unroll
    for (int half = 0; half < 2; half++) {
        float ss = 0.0f;
#pragma unroll
        for (int j = 0; j < 8; j++)
            ss += acc[j][half * 2] * acc[j][half * 2] +
                  acc[j][half * 2 + 1] * acc[j][half * 2 + 1];
        ss += __shfl_xor_sync(0xFFFFFFFF, ss, 1);
        ss += __shfl_xor_sync(0xFFFFFFFF, ss, 2);
        float n = sqrtf(ss) * 0.125f;
        float inv = 1.0f / fmaxf(n, 1e-12f);
        int r = warpM + (lane >> 2) + half * 8;
#pragma unroll
        for (int j = 0; j < 8; j++) {
            int c = j * 8 + (lane & 3) * 2;
            float2 uv = *(const float2*)(g_uF + ub + r * 64 + c);
            float y0 = acc[j][half * 2] * inv * uv.x;
            float y1 = acc[j][half * 2 + 1] * inv * uv.y;
            __half2 yy = __floats2half2_rn(y0, y1);
            *(__half2*)((char*)g_yf + yb + swz(r * 128 + c * 2)) = yy;
        }
    }
}

// ---------------------------------------------------------------------------
extern "C" void kernel_launch(void* const* d_in, const int* in_sizes, int n_in,
                              void* d_out, int out_size) {
    const float* x  = (const float*)d_in[0];
    const float* Wq = (const float*)d_in[1];
    const float* Wk = (const float*)d_in[2];
    const float* Wv = (const float*)d_in[3];
    const float* Wu = (const float*)d_in[4];
    const float* Wo = (const float*)d_in[5];
    float* out = (float*)d_out;

    cudaFuncSetAttribute(proj_mma, cudaFuncAttributeMaxDynamicSharedMemorySize, GSMEM);
    cudaFuncSetAttribute(fin_mma,  cudaFuncAttributeMaxDynamicSharedMemorySize, GSMEM);
    cudaFuncSetAttribute(kv_mma,   cudaFuncAttributeMaxDynamicSharedMemorySize, 65536);
    cudaFuncSetAttribute(out_mma,  cudaFuncAttributeMaxDynamicSharedMemorySize, 49152);

    split_x_kernel<<<8192, 256>>>(x);
    split_w_kernel<<<2560, 256>>>(Wq, Wk, Wv, Wu, Wo);
    zero_kv_kernel<<<1024, 256>>>();
    proj_mma<<<dim3(128, 8, 4), 256, GSMEM>>>();
    kv_mma<<<dim3(NBH, 8), 128, 65536>>>();
    kv_split<<<NBH, 256>>>();
    out_mma<<<dim3(128, 16), 256, 49152>>>();
    fin_mma<<<dim3(128, 8), 256, GSMEM>>>(out);
}

// round 11
// speedup vs baseline: 7.0622x; 1.5755x over previous
#include <cuda_runtime.h>
#include <cuda_fp16.h>
#include <math.h>
#include <stdint.h>

#define NROWS 16384      // b*l = 4*4096
#define EMB   1024
#define HD    64
#define NBH   64         // b*h
#define LSEQ  4096
#define KT    16         // K chunks of 64
#define TILE_ELEMS 8192  // 128 rows * 64 fp16
#define TILE_BYTES 16384
#define WSZ (8*16*8192)  // per-weight tiled elems (1024*1024)
#define STAGES 3
#define STAGE_BYTES (2*TILE_BYTES)   // A | B = 32KB
#define GSMEM (STAGES*STAGE_BYTES)   // 98304 -> 2 CTAs/SM

using f16 = __half;

// ---------------- scratch (device globals; allocation-free) ----------------
__device__ __align__(128) f16   g_xf[NROWS * EMB];    // x fp16 tiled
__device__ __align__(128) f16   g_yf[NROWS * EMB];    // y fp16 tiled
__device__ __align__(128) f16   g_wf[5 * WSZ];        // W fp16 tiled (single)
__device__ __align__(128) f16   g_qh[NROWS * EMB];    // q hi, head-tiled
__device__ __align__(128) f16   g_ql[NROWS * EMB];    // q lo
__device__ __align__(128) float g_uF[NROWS * EMB];    // u fp32, head-tiled
__device__ __align__(128) f16   g_kTh[NROWS * EMB];   // k^T hi  [bh][lc][a64][l64]
__device__ __align__(128) f16   g_kTl[NROWS * EMB];
__device__ __align__(128) f16   g_vTh[NROWS * EMB];   // v^T hi
__device__ __align__(128) f16   g_vTl[NROWS * EMB];
__device__ __align__(128) float g_kvT[NBH * HD * HD]; // kv^T fp32 accum
__device__ __align__(128) f16   g_kvh[NBH * HD * HD]; // kv^T hi tiles
__device__ __align__(128) f16   g_kvl[NBH * HD * HD];

// ---------------- helpers ----------------
__device__ __forceinline__ uint32_t s2u(const void* p) {
    uint32_t a;
    asm("{ .reg .u64 t; cvta.to.shared.u64 t, %1; cvt.u32.u64 %0, t; }" : "=r"(a) : "l"(p));
    return a;
}
__device__ __forceinline__ uint32_t swz(uint32_t off) { return off ^ ((off >> 3) & 0x70); }

__device__ __forceinline__ void cpa16(uint32_t saddr, const void* gaddr) {
    asm volatile("cp.async.cg.shared.global [%0], [%1], 16;" :: "r"(saddr), "l"(gaddr) : "memory");
}
__device__ __forceinline__ void cpa_commit() {
    asm volatile("cp.async.commit_group;" ::: "memory");
}
__device__ __forceinline__ void cpa_wait2() {
    asm volatile("cp.async.wait_group 2;" ::: "memory");
}
__device__ __forceinline__ void cpa_wait1() {
    asm volatile("cp.async.wait_group 1;" ::: "memory");
}
__device__ __forceinline__ void cpa_wait0() {
    asm volatile("cp.async.wait_group 0;" ::: "memory");
}
__device__ __forceinline__ void ldsm4(uint32_t& r0, uint32_t& r1, uint32_t& r2, uint32_t& r3,
                                      uint32_t addr) {
    asm volatile("ldmatrix.sync.aligned.m8n8.x4.shared.b16 {%0,%1,%2,%3}, [%4];"
                 : "=r"(r0), "=r"(r1), "=r"(r2), "=r"(r3) : "r"(addr));
}
__device__ __forceinline__ void mma16816(float* c, uint32_t a0, uint32_t a1, uint32_t a2,
                                         uint32_t a3, uint32_t b0, uint32_t b1) {
    asm volatile(
        "mma.sync.aligned.m16n8k16.row.col.f32.f16.f16.f32 "
        "{%0,%1,%2,%3},{%4,%5,%6,%7},{%8,%9},{%0,%1,%2,%3};"
        : "+f"(c[0]), "+f"(c[1]), "+f"(c[2]), "+f"(c[3])
        : "r"(a0), "r"(a1), "r"(a2), "r"(a3), "r"(b0), "r"(b1));
}

__device__ __forceinline__ uint4 conv8h(const float* v) {
    unsigned int u[4];
#pragma unroll
    for (int j = 0; j < 4; j++) {
        u[j] = (unsigned)__half_as_ushort(__float2half_rn(v[2 * j])) |
               ((unsigned)__half_as_ushort(__float2half_rn(v[2 * j + 1])) << 16);
    }
    return make_uint4(u[0], u[1], u[2], u[3]);
}
__device__ __forceinline__ void split8h(const float* v, uint4& h, uint4& l) {
    unsigned int hu[4], lu[4];
#pragma unroll
    for (int j = 0; j < 4; j++) {
        float a = v[2 * j], b = v[2 * j + 1];
        f16 ah = __float2half_rn(a), bh = __float2half_rn(b);
        float ar = a - __half2float(ah), br = b - __half2float(bh);
        f16 al = __float2half_rn(ar), bl = __float2half_rn(br);
        hu[j] = (unsigned)__half_as_ushort(ah) | ((unsigned)__half_as_ushort(bh) << 16);
        lu[j] = (unsigned)__half_as_ushort(al) | ((unsigned)__half_as_ushort(bl) << 16);
    }
    h = make_uint4(hu[0], hu[1], hu[2], hu[3]);
    l = make_uint4(lu[0], lu[1], lu[2], lu[3]);
}
__device__ __forceinline__ void split2h(float v0, float v1, uint32_t& hv, uint32_t& lv) {
    f16 h0 = __float2half_rn(v0), h1 = __float2half_rn(v1);
    f16 l0 = __float2half_rn(v0 - __half2float(h0));
    f16 l1 = __float2half_rn(v1 - __half2float(h1));
    hv = (unsigned)__half_as_ushort(h0) | ((unsigned)__half_as_ushort(h1) << 16);
    lv = (unsigned)__half_as_ushort(l0) | ((unsigned)__half_as_ushort(l1) << 16);
}

// ---------------- convert kernels ----------------
__global__ __launch_bounds__(256) void split_x_kernel(const float* __restrict__ X) {
    int i = blockIdx.x * 256 + threadIdx.x;
    int row = i >> 7, c = i & 127;
    int kt = c >> 3, ci = c & 7;
    const float4* p = (const float4*)(X + (size_t)row * EMB + kt * 64 + ci * 8);
    float vv[8];
    *(float4*)&vv[0] = p[0];
    *(float4*)&vv[4] = p[1];
    uint4 h = conv8h(vv);
    int mt = row >> 7, r = row & 127;
    uint32_t off = swz(r * 128 + ci * 16);
    size_t base = ((size_t)(mt * KT + kt)) * TILE_ELEMS;
    *(uint4*)((char*)g_xf + base * 2 + off) = h;
}

__global__ __launch_bounds__(256) void split_w_kernel(const float* __restrict__ Wq,
                                                      const float* __restrict__ Wk,
                                                      const float* __restrict__ Wv,
                                                      const float* __restrict__ Wu,
                                                      const float* __restrict__ Wo) {
    int i = blockIdx.x * 256 + threadIdx.x;
    int row = i >> 7, c = i & 127;
    int widx = row >> 10, r = row & 1023;
    int kt = c >> 3, ci = c & 7;
    const float* W = (widx == 0) ? Wq : (widx == 1) ? Wk : (widx == 2) ? Wv : (widx == 3) ? Wu : Wo;
    const float4* p = (const float4*)(W + (size_t)r * EMB + kt * 64 + ci * 8);
    float vv[8];
    *(float4*)&vv[0] = p[0];
    *(float4*)&vv[4] = p[1];
    uint4 h = conv8h(vv);
    int nt = r >> 7, rr = r & 127;
    uint32_t off = swz(rr * 128 + ci * 16);
    size_t base = (size_t)widx * WSZ + ((size_t)(nt * KT + kt)) * TILE_ELEMS;
    *(uint4*)((char*)g_wf + base * 2 + off) = h;
}

__global__ void zero_kv_kernel() {
    int i = blockIdx.x * 256 + threadIdx.x;
    if (i < NBH * HD * HD) g_kvT[i] = 0.0f;
}

// ---------------- proj GEMM: 128x128 CTA, BK=64, 3-stage, fused epilogues --
__global__ __launch_bounds__(256, 2) void proj_mma() {
    extern __shared__ char sm[];
    uint32_t sb = s2u(sm);
    const int tid = threadIdx.x, lane = tid & 31, wid = tid >> 5;
    const int mt = blockIdx.x, nt = blockIdx.y, z = blockIdx.z;
    const int warpM = (wid >> 2) * 64;
    const int warpN = (wid & 3) * 32;
    const f16* Bg = g_wf + (size_t)z * WSZ;

    auto load_stage = [&](int s, int kc) {
        uint32_t d = sb + s * STAGE_BYTES;
        size_t at = ((size_t)(mt * KT + kc)) * TILE_ELEMS;
        size_t bt = ((size_t)(nt * KT + kc)) * TILE_ELEMS;
        const char* srcs[2] = {(const char*)(g_xf + at), (const char*)(Bg + bt)};
#pragma unroll
        for (int blk = 0; blk < 2; blk++)
#pragma unroll
            for (int i = 0; i < 4; i++)
                cpa16(d + blk * TILE_BYTES + i * 4096 + tid * 16,
                      srcs[blk] + i * 4096 + tid * 16);
        cpa_commit();
    };

    float acc[4][4][4];
#pragma unroll
    for (int i = 0; i < 4; i++)
#pragma unroll
        for (int j = 0; j < 4; j++)
#pragma unroll
            for (int e = 0; e < 4; e++) acc[i][j][e] = 0.0f;

    const int aRow = warpM + (lane & 15);
    const int aKg  = (lane >> 4);
    const int bRow = warpN + ((lane >> 4) << 3) + (lane & 7);
    const int bKg  = ((lane >> 3) & 1);

    load_stage(0, 0);
    load_stage(1, 1);
    load_stage(2, 2);

    for (int kc = 0; kc < KT; kc++) {
        int cur = kc % STAGES;
        if (kc + 2 < KT) cpa_wait2();
        else if (kc + 1 < KT) cpa_wait1();
        else cpa_wait0();
        __syncthreads();

        uint32_t A = sb + cur * STAGE_BYTES;
        uint32_t B = A + TILE_BYTES;

#pragma unroll
        for (int kk = 0; kk < 4; kk++) {
            uint32_t aX[4][4], bF[4][2];
#pragma unroll
            for (int i = 0; i < 4; i++)
                ldsm4(aX[i][0], aX[i][1], aX[i][2], aX[i][3],
                      A + swz((aRow + i * 16) * 128 + (kk * 2 + aKg) * 16));
#pragma unroll
            for (int jj = 0; jj < 2; jj++) {
                uint32_t boff = swz((bRow + jj * 16) * 128 + (kk * 2 + bKg) * 16);
                ldsm4(bF[2 * jj][0], bF[2 * jj][1],
                      bF[2 * jj + 1][0], bF[2 * jj + 1][1], B + boff);
            }
#pragma unroll
            for (int i = 0; i < 4; i++)
#pragma unroll
                for (int j = 0; j < 4; j++)
                    mma16816(acc[i][j], aX[i][0], aX[i][1], aX[i][2], aX[i][3],
                             bF[j][0], bF[j][1]);
        }
        __syncthreads();
        if (kc + 3 < KT) load_stage(cur, kc + 3);
    }

    // ---- epilogues ----
    if (z == 0 || z == 3) {
        // q: relu*0.125, split hi/lo fp16 head-tiles.  u: silu, fp32 head-tiles.
#pragma unroll
        for (int i = 0; i < 4; i++) {
#pragma unroll
            for (int j = 0; j < 4; j++) {
#pragma unroll
                for (int half = 0; half < 2; half++) {
                    int r = warpM + i * 16 + (lane >> 2) + half * 8;
                    int c = warpN + j * 8 + (lane & 3) * 2;
                    int h = c >> 6, cin = c & 63;
                    float v0 = acc[i][j][half * 2 + 0];
                    float v1 = acc[i][j][half * 2 + 1];
                    size_t tile = (size_t)mt * 16 + (nt * 2 + h);
                    if (z == 0) {
                        v0 = fmaxf(v0, 0.f) * 0.125f;
                        v1 = fmaxf(v1, 0.f) * 0.125f;
                        uint32_t hv, lv;
                        split2h(v0, v1, hv, lv);
                        size_t base = tile * TILE_ELEMS * 2;
                        uint32_t off = swz(r * 128 + cin * 2);
                        *(uint32_t*)((char*)g_qh + base + off) = hv;
                        *(uint32_t*)((char*)g_ql + base + off) = lv;
                    } else {
                        v0 = v0 / (1.f + expf(-v0));
                        v1 = v1 / (1.f + expf(-v1));
                        *(float2*)(g_uF + tile * TILE_ELEMS + r * 64 + cin) =
                            make_float2(v0, v1);
                    }
                }
            }
        }
    } else {
        // k (z=1): relu*0.125;  v (z=2): identity. Transpose via smem, split hi/lo.
        float* smf = (float*)sm;   // 128 x 130 fp32 stage (66.5KB < 96KB)
        __syncthreads();
#pragma unroll
        for (int i = 0; i < 4; i++) {
#pragma unroll
            for (int j = 0; j < 4; j++) {
#pragma unroll
                for (int half = 0; half < 2; half++) {
                    int r = warpM + i * 16 + (lane >> 2) + half * 8;
                    int c = warpN + j * 8 + (lane & 3) * 2;
                    float v0 = acc[i][j][half * 2 + 0];
                    float v1 = acc[i][j][half * 2 + 1];
                    if (z == 1) {
                        v0 = fmaxf(v0, 0.f) * 0.125f;
                        v1 = fmaxf(v1, 0.f) * 0.125f;
                    }
                    *(float2*)&smf[r * 130 + c] = make_float2(v0, v1);
                }
            }
        }
        __syncthreads();
        int a = tid & 63, hl = (tid >> 6) & 1, lcl = tid >> 7;
        float vv[64];
#pragma unroll
        for (int l = 0; l < 64; l++)
            vv[l] = smf[(lcl * 64 + l) * 130 + hl * 64 + a];
        int b = mt >> 5;
        int bh = b * 16 + nt * 2 + hl;
        int lc = (mt & 31) * 2 + lcl;
        size_t base = (((size_t)bh * 64 + lc) * 4096) * 2;
        f16* dh = (z == 1) ? g_kTh : g_vTh;
        f16* dl = (z == 1) ? g_kTl : g_vTl;
#pragma unroll
        for (int g = 0; g < 8; g++) {
            uint4 hq, lq;
            split8h(&vv[g * 8], hq, lq);
            uint32_t off = swz(a * 128 + g * 16);
            *(uint4*)((char*)dh + base + off) = hq;
            *(uint4*)((char*)dl + base + off) = lq;
        }
    }
}

// ---------------- fin GEMM: single-product, 3-stage ----------------
__global__ __launch_bounds__(256, 2) void fin_mma(float* __restrict__ C) {
    extern __shared__ char sm[];
    uint32_t sb = s2u(sm);
    const int tid = threadIdx.x, lane = tid & 31, wid = tid >> 5;
    const int mt = blockIdx.x, nt = blockIdx.y;
    const int warpM = (wid >> 2) * 64;
    const int warpN = (wid & 3) * 32;
    const f16* Bg = g_wf + (size_t)4 * WSZ;

    auto load_stage = [&](int s, int kc) {
        uint32_t d = sb + s * STAGE_BYTES;
        size_t at = ((size_t)(mt * KT + kc)) * TILE_ELEMS;
        size_t bt = ((size_t)(nt * KT + kc)) * TILE_ELEMS;
        const char* srcs[2] = {(const char*)(g_yf + at), (const char*)(Bg + bt)};
#pragma unroll
        for (int blk = 0; blk < 2; blk++)
#pragma unroll
            for (int i = 0; i < 4; i++)
                cpa16(d + blk * TILE_BYTES + i * 4096 + tid * 16,
                      srcs[blk] + i * 4096 + tid * 16);
        cpa_commit();
    };

    float acc[4][4][4];
#pragma unroll
    for (int i = 0; i < 4; i++)
#pragma unroll
        for (int j = 0; j < 4; j++)
#pragma unroll
            for (int e = 0; e < 4; e++) acc[i][j][e] = 0.0f;

    const int aRow = warpM + (lane & 15);
    const int aKg  = (lane >> 4);
    const int bRow = warpN + ((lane >> 4) << 3) + (lane & 7);
    const int bKg  = ((lane >> 3) & 1);

    load_stage(0, 0);
    load_stage(1, 1);
    load_stage(2, 2);

    for (int kc = 0; kc < KT; kc++) {
        int cur = kc % STAGES;
        if (kc + 2 < KT) cpa_wait2();
        else if (kc + 1 < KT) cpa_wait1();
        else cpa_wait0();
        __syncthreads();

        uint32_t A = sb + cur * STAGE_BYTES;
        uint32_t B = A + TILE_BYTES;

#pragma unroll
        for (int kk = 0; kk < 4; kk++) {
            uint32_t aX[4][4], bF[4][2];
#pragma unroll
            for (int i = 0; i < 4; i++)
                ldsm4(aX[i][0], aX[i][1], aX[i][2], aX[i][3],
                      A + swz((aRow + i * 16) * 128 + (kk * 2 + aKg) * 16));
#pragma unroll
            for (int jj = 0; jj < 2; jj++) {
                uint32_t boff = swz((bRow + jj * 16) * 128 + (kk * 2 + bKg) * 16);
                ldsm4(bF[2 * jj][0], bF[2 * jj][1],
                      bF[2 * jj + 1][0], bF[2 * jj + 1][1], B + boff);
            }
#pragma unroll
            for (int i = 0; i < 4; i++)
#pragma unroll
                for (int j = 0; j < 4; j++)
                    mma16816(acc[i][j], aX[i][0], aX[i][1], aX[i][2], aX[i][3],
                             bF[j][0], bF[j][1]);
        }
        __syncthreads();
        if (kc + 3 < KT) load_stage(cur, kc + 3);
    }

#pragma unroll
    for (int i = 0; i < 4; i++)
#pragma unroll
        for (int j = 0; j < 4; j++)
#pragma unroll
            for (int half = 0; half < 2; half++) {
                int row = mt * 128 + warpM + i * 16 + (lane >> 2) + half * 8;
                int col = nt * 128 + warpN + j * 8 + (lane & 3) * 2;
                *(float2*)(C + (size_t)row * EMB + col) =
                    make_float2(acc[i][j][half * 2], acc[i][j][half * 2 + 1]);
            }
}

// ---------------- kv via mma: kvT[b][a] += sum_l v[l,b]*k[l,a] ----------------
__global__ __launch_bounds__(128, 3) void kv_mma() {
    extern __shared__ char sm[];
    uint32_t sb = s2u(sm);
    const int tid = threadIdx.x, lane = tid & 31, wid = tid >> 5;
    const int bh = blockIdx.x, split = blockIdx.y;
    const int warpM = (wid >> 1) * 32;
    const int warpN = (wid & 1) * 32;

    auto load_stage = [&](int s, int ch) {
        int lc = split * 8 + ch;
        size_t tb = (((size_t)bh * 64 + lc) * 4096) * 2;   // tile byte offset
        const char* srcs[4] = {(const char*)g_vTh + tb, (const char*)g_vTl + tb,
                               (const char*)g_kTh + tb, (const char*)g_kTl + tb};
        uint32_t d = sb + s * 32768;
#pragma unroll
        for (int blk = 0; blk < 4; blk++)
#pragma unroll
            for (int i = 0; i < 4; i++)
                cpa16(d + blk * 8192 + i * 2048 + tid * 16,
                      srcs[blk] + i * 2048 + tid * 16);
        cpa_commit();
    };

    float acc[2][4][4];
#pragma unroll
    for (int i = 0; i < 2; i++)
#pragma unroll
        for (int j = 0; j < 4; j++)
#pragma unroll
            for (int e = 0; e < 4; e++) acc[i][j][e] = 0.0f;

    const int aRow = warpM + (lane & 15);
    const int aKg  = (lane >> 4);
    const int bRow = warpN + ((lane >> 4) << 3) + (lane & 7);
    const int bKg  = ((lane >> 3) & 1);

    load_stage(0, 0);
    load_stage(1, 1);

    for (int ch = 0; ch < 8; ch++) {
        int cur = ch & 1;
        if (ch + 1 < 8) cpa_wait1(); else cpa_wait0();
        __syncthreads();
        uint32_t Avh = sb + cur * 32768;
        uint32_t Avl = Avh + 8192, Bkh = Avh + 16384, Bkl = Avh + 24576;

#pragma unroll
        for (int kk = 0; kk < 4; kk++) {
            uint32_t avh[2][4], avl[2][4], bkh[4][2], bkl[4][2];
#pragma unroll
            for (int i = 0; i < 2; i++) {
                uint32_t aoff = swz((aRow + i * 16) * 128 + (kk * 2 + aKg) * 16);
                ldsm4(avh[i][0], avh[i][1], avh[i][2], avh[i][3], Avh + aoff);
                ldsm4(avl[i][0], avl[i][1], avl[i][2], avl[i][3], Avl + aoff);
            }
#pragma unroll
            for (int jj = 0; jj < 2; jj++) {
                uint32_t boff = swz((bRow + jj * 16) * 128 + (kk * 2 + bKg) * 16);
                ldsm4(bkh[2 * jj][0], bkh[2 * jj][1],
                      bkh[2 * jj + 1][0], bkh[2 * jj + 1][1], Bkh + boff);
                ldsm4(bkl[2 * jj][0], bkl[2 * jj][1],
                      bkl[2 * jj + 1][0], bkl[2 * jj + 1][1], Bkl + boff);
            }
#pragma unroll
            for (int i = 0; i < 2; i++)
#pragma unroll
                for (int j = 0; j < 4; j++) {
                    mma16816(acc[i][j], avh[i][0], avh[i][1], avh[i][2], avh[i][3],
                             bkh[j][0], bkh[j][1]);
                    mma16816(acc[i][j], avh[i][0], avh[i][1], avh[i][2], avh[i][3],
                             bkl[j][0], bkl[j][1]);
                    mma16816(acc[i][j], avl[i][0], avl[i][1], avl[i][2], avl[i][3],
                             bkh[j][0], bkh[j][1]);
                }
        }
        __syncthreads();
        if (ch + 2 < 8) load_stage(cur, ch + 2);
    }

    float* kvp = g_kvT + (size_t)bh * 4096;
#pragma unroll
    for (int i = 0; i < 2; i++)
#pragma unroll
        for (int j = 0; j < 4; j++)
#pragma unroll
            for (int half = 0; half < 2; half++) {
                int row = warpM + i * 16 + (lane >> 2) + half * 8;
                int col = warpN + j * 8 + (lane & 3) * 2;
                atomicAdd(kvp + row * 64 + col,     acc[i][j][half * 2]);
                atomicAdd(kvp + row * 64 + col + 1, acc[i][j][half * 2 + 1]);
            }
}

// ---------------- kvT fp32 -> hi/lo fp16 swizzled tiles ----------------
__global__ __launch_bounds__(256) void kv_split() {
    int bh = blockIdx.x, t = threadIdx.x;
    int row = t >> 2, c0 = (t & 3) * 16;
    const float* src = g_kvT + (size_t)bh * 4096 + row * 64 + c0;
    float vv[16];
#pragma unroll
    for (int g = 0; g < 4; g++) *(float4*)&vv[g * 4] = ((const float4*)src)[g];
    size_t base = ((size_t)bh * 4096) * 2;
#pragma unroll
    for (int g = 0; g < 2; g++) {
        uint4 hq, lq;
        split8h(&vv[g * 8], hq, lq);
        uint32_t off = swz(row * 128 + c0 * 2 + g * 16);
        *(uint4*)((char*)g_kvh + base + off) = hq;
        *(uint4*)((char*)g_kvl + base + off) = lq;
    }
}

// ---------------- out = q@kv; SRMSNorm; *u; write fp16 y tiles ----------------
__global__ __launch_bounds__(256) void out_mma() {
    extern __shared__ char sm[];
    uint32_t sb = s2u(sm);
    const int tid = threadIdx.x, lane = tid & 31, wid = tid >> 5;
    const int mt = blockIdx.x, h = blockIdx.y;
    const int bh = (mt >> 5) * 16 + h;
    const size_t qbase = ((size_t)mt * 16 + h) * TILE_ELEMS * 2;    // bytes
    const size_t kvbase = ((size_t)bh * 4096) * 2;

    // single-shot loads: qh(16K) ql(16K) kvh(8K) kvl(8K)
#pragma unroll
    for (int i = 0; i < 4; i++) {
        cpa16(sb + i * 4096 + tid * 16, (const char*)g_qh + qbase + i * 4096 + tid * 16);
        cpa16(sb + 16384 + i * 4096 + tid * 16,
              (const char*)g_ql + qbase + i * 4096 + tid * 16);
    }
#pragma unroll
    for (int i = 0; i < 2; i++) {
        cpa16(sb + 32768 + i * 4096 + tid * 16,
              (const char*)g_kvh + kvbase + i * 4096 + tid * 16);
        cpa16(sb + 40960 + i * 4096 + tid * 16,
              (const char*)g_kvl + kvbase + i * 4096 + tid * 16);
    }
    cpa_commit();
    cpa_wait0();
    __syncthreads();

    const int warpM = wid * 16;
    const int aRow = warpM + (lane & 15);
    const int aKg  = (lane >> 4);
    const int bRow = ((lane >> 4) << 3) + (lane & 7);
    const int bKg  = ((lane >> 3) & 1);
    const uint32_t Qh = sb, Ql = sb + 16384, Kh = sb + 32768, Kl = sb + 40960;

    float acc[8][4];
#pragma unroll
    for (int j = 0; j < 8; j++)
#pragma unroll
        for (int e = 0; e < 4; e++) acc[j][e] = 0.0f;

#pragma unroll
    for (int kk = 0; kk < 4; kk++) {
        uint32_t aqh[4], aql[4], bvh[8][2], bvl[8][2];
        uint32_t aoff = swz(aRow * 128 + (kk * 2 + aKg) * 16);
        ldsm4(aqh[0], aqh[1], aqh[2], aqh[3], Qh + aoff);
        ldsm4(aql[0], aql[1], aql[2], aql[3], Ql + aoff);
#pragma unroll
        for (int jj = 0; jj < 4; jj++) {
            uint32_t boff = swz((jj * 16 + bRow) * 128 + (kk * 2 + bKg) * 16);
            ldsm4(bvh[2 * jj][0], bvh[2 * jj][1],
                  bvh[2 * jj + 1][0], bvh[2 * jj + 1][1], Kh + boff);
            ldsm4(bvl[2 * jj][0], bvl[2 * jj][1],
                  bvl[2 * jj + 1][0], bvl[2 * jj + 1][1], Kl + boff);
        }
#pragma unroll
        for (int j = 0; j < 8; j++) {
            mma16816(acc[j], aqh[0], aqh[1], aqh[2], aqh[3], bvh[j][0], bvh[j][1]);
            mma16816(acc[j], aqh[0], aqh[1], aqh[2], aqh[3], bvl[j][0], bvl[j][1]);
            mma16816(acc[j], aql[0], aql[1], aql[2], aql[3], bvh[j][0], bvh[j][1]);
        }
    }

    // row-wise SRMSNorm + u-multiply + fp16 tiled y store
    const size_t ub = ((size_t)mt * 16 + h) * TILE_ELEMS;           // fp32 elems
    const size_t yb = ((size_t)mt * 16 + h) * TILE_ELEMS * 2;       // bytes
#pragma unroll
    for (int half = 0; half < 2; half++) {
        float ss = 0.0f;
#pragma unroll
        for (int j = 0; j < 8; j++)
            ss += acc[j][half * 2] * acc[j][half * 2] +
                  acc[j][half * 2 + 1] * acc[j][half * 2 + 1];
        ss += __shfl_xor_sync(0xFFFFFFFF, ss, 1);
        ss += __shfl_xor_sync(0xFFFFFFFF, ss, 2);
        float n = sqrtf(ss) * 0.125f;
        float inv = 1.0f / fmaxf(n, 1e-12f);
        int r = warpM + (lane >> 2) + half * 8;
#pragma unroll
        for (int j = 0; j < 8; j++) {
            int c = j * 8 + (lane & 3) * 2;
            float2 uv = *(const float2*)(g_uF + ub + r * 64 + c);
            float y0 = acc[j][half * 2] * inv * uv.x;
            float y1 = acc[j][half * 2 + 1] * inv * uv.y;
            __half2 yy = __floats2half2_rn(y0, y1);
            *(__half2*)((char*)g_yf + yb + swz(r * 128 + c * 2)) = yy;
        }
    }
}

// ---------------------------------------------------------------------------
extern "C" void kernel_launch(void* const* d_in, const int* in_sizes, int n_in,
                              void* d_out, int out_size) {
    const float* x  = (const float*)d_in[0];
    const float* Wq = (const float*)d_in[1];
    const float* Wk = (const float*)d_in[2];
    const float* Wv = (const float*)d_in[3];
    const float* Wu = (const float*)d_in[4];
    const float* Wo = (const float*)d_in[5];
    float* out = (float*)d_out;

    cudaFuncSetAttribute(proj_mma, cudaFuncAttributeMaxDynamicSharedMemorySize, GSMEM);
    cudaFuncSetAttribute(fin_mma,  cudaFuncAttributeMaxDynamicSharedMemorySize, GSMEM);
    cudaFuncSetAttribute(kv_mma,   cudaFuncAttributeMaxDynamicSharedMemorySize, 65536);
    cudaFuncSetAttribute(out_mma,  cudaFuncAttributeMaxDynamicSharedMemorySize, 49152);

    split_x_kernel<<<8192, 256>>>(x);
    split_w_kernel<<<2560, 256>>>(Wq, Wk, Wv, Wu, Wo);
    zero_kv_kernel<<<1024, 256>>>();
    proj_mma<<<dim3(128, 8, 4), 256, GSMEM>>>();
    kv_mma<<<dim3(NBH, 8), 128, 65536>>>();
    kv_split<<<NBH, 256>>>();
    out_mma<<<dim3(128, 16), 256, 49152>>>();
    fin_mma<<<dim3(128, 8), 256, GSMEM>>>(out);
}

// round 12
// speedup vs baseline: 7.4552x; 1.0557x over previous
#include <cuda_runtime.h>
#include <cuda_fp16.h>
#include <math.h>
#include <stdint.h>

#define NROWS 16384      // b*l = 4*4096
#define EMB   1024
#define HD    64
#define NBH   64         // b*h
#define LSEQ  4096
#define KT    16         // K chunks of 64
#define TILE_ELEMS 8192  // 128 rows * 64 fp16
#define TILE_BYTES 16384
#define WSZ (8*16*8192)  // per-weight tiled elems (1024*1024)
#define STAGES 3
#define STAGE_BYTES (2*TILE_BYTES)   // A | B = 32KB
#define GSMEM (STAGES*STAGE_BYTES)   // 98304 -> 2 CTAs/SM

using f16 = __half;

// ---------------- scratch (device globals; allocation-free) ----------------
__device__ __align__(128) f16   g_xf[NROWS * EMB];    // x fp16 tiled
__device__ __align__(128) f16   g_yf[NROWS * EMB];    // y fp16 tiled
__device__ __align__(128) f16   g_wf[5 * WSZ];        // W fp16 tiled (single)
__device__ __align__(128) f16   g_qh[NROWS * EMB];    // q hi, head-tiled
__device__ __align__(128) f16   g_ql[NROWS * EMB];    // q lo
__device__ __align__(128) f16   g_kh[NROWS * EMB];    // k hi, head-tiled
__device__ __align__(128) f16   g_kl[NROWS * EMB];
__device__ __align__(128) f16   g_vh[NROWS * EMB];    // v hi, head-tiled
__device__ __align__(128) f16   g_vl[NROWS * EMB];
__device__ __align__(128) float g_uF[NROWS * EMB];    // u fp32, head-tiled
__device__ __align__(128) float g_kvT[NBH * HD * HD]; // kv^T fp32 accum
__device__ __align__(128) f16   g_kvh[NBH * HD * HD]; // kv^T hi tiles
__device__ __align__(128) f16   g_kvl[NBH * HD * HD];

// ---------------- helpers ----------------
__device__ __forceinline__ uint32_t s2u(const void* p) {
    uint32_t a;
    asm("{ .reg .u64 t; cvta.to.shared.u64 t, %1; cvt.u32.u64 %0, t; }" : "=r"(a) : "l"(p));
    return a;
}
__device__ __forceinline__ uint32_t swz(uint32_t off) { return off ^ ((off >> 3) & 0x70); }

__device__ __forceinline__ void cpa16(uint32_t saddr, const void* gaddr) {
    asm volatile("cp.async.cg.shared.global [%0], [%1], 16;" :: "r"(saddr), "l"(gaddr) : "memory");
}
__device__ __forceinline__ void cpa_commit() {
    asm volatile("cp.async.commit_group;" ::: "memory");
}
__device__ __forceinline__ void cpa_wait1() {
    asm volatile("cp.async.wait_group 1;" ::: "memory");
}
__device__ __forceinline__ void cpa_wait0() {
    asm volatile("cp.async.wait_group 0;" ::: "memory");
}
__device__ __forceinline__ void ldsm4(uint32_t& r0, uint32_t& r1, uint32_t& r2, uint32_t& r3,
                                      uint32_t addr) {
    asm volatile("ldmatrix.sync.aligned.m8n8.x4.shared.b16 {%0,%1,%2,%3}, [%4];"
                 : "=r"(r0), "=r"(r1), "=r"(r2), "=r"(r3) : "r"(addr));
}
__device__ __forceinline__ void ldsm4t(uint32_t& r0, uint32_t& r1, uint32_t& r2, uint32_t& r3,
                                       uint32_t addr) {
    asm volatile("ldmatrix.sync.aligned.m8n8.x4.trans.shared.b16 {%0,%1,%2,%3}, [%4];"
                 : "=r"(r0), "=r"(r1), "=r"(r2), "=r"(r3) : "r"(addr));
}
__device__ __forceinline__ void mma16816(float* c, uint32_t a0, uint32_t a1, uint32_t a2,
                                         uint32_t a3, uint32_t b0, uint32_t b1) {
    asm volatile(
        "mma.sync.aligned.m16n8k16.row.col.f32.f16.f16.f32 "
        "{%0,%1,%2,%3},{%4,%5,%6,%7},{%8,%9},{%0,%1,%2,%3};"
        : "+f"(c[0]), "+f"(c[1]), "+f"(c[2]), "+f"(c[3])
        : "r"(a0), "r"(a1), "r"(a2), "r"(a3), "r"(b0), "r"(b1));
}

__device__ __forceinline__ uint4 conv8h(const float* v) {
    unsigned int u[4];
#pragma unroll
    for (int j = 0; j < 4; j++) {
        u[j] = (unsigned)__half_as_ushort(__float2half_rn(v[2 * j])) |
               ((unsigned)__half_as_ushort(__float2half_rn(v[2 * j + 1])) << 16);
    }
    return make_uint4(u[0], u[1], u[2], u[3]);
}
__device__ __forceinline__ void split8h(const float* v, uint4& h, uint4& l) {
    unsigned int hu[4], lu[4];
#pragma unroll
    for (int j = 0; j < 4; j++) {
        float a = v[2 * j], b = v[2 * j + 1];
        f16 ah = __float2half_rn(a), bh = __float2half_rn(b);
        float ar = a - __half2float(ah), br = b - __half2float(bh);
        f16 al = __float2half_rn(ar), bl = __float2half_rn(br);
        hu[j] = (unsigned)__half_as_ushort(ah) | ((unsigned)__half_as_ushort(bh) << 16);
        lu[j] = (unsigned)__half_as_ushort(al) | ((unsigned)__half_as_ushort(bl) << 16);
    }
    h = make_uint4(hu[0], hu[1], hu[2], hu[3]);
    l = make_uint4(lu[0], lu[1], lu[2], lu[3]);
}
__device__ __forceinline__ void split2h(float v0, float v1, uint32_t& hv, uint32_t& lv) {
    f16 h0 = __float2half_rn(v0), h1 = __float2half_rn(v1);
    f16 l0 = __float2half_rn(v0 - __half2float(h0));
    f16 l1 = __float2half_rn(v1 - __half2float(h1));
    hv = (unsigned)__half_as_ushort(h0) | ((unsigned)__half_as_ushort(h1) << 16);
    lv = (unsigned)__half_as_ushort(l0) | ((unsigned)__half_as_ushort(l1) << 16);
}

// ---------------- convert kernels ----------------
__global__ __launch_bounds__(256) void split_x_kernel(const float* __restrict__ X) {
    int i = blockIdx.x * 256 + threadIdx.x;
    int row = i >> 7, c = i & 127;
    int kt = c >> 3, ci = c & 7;
    const float4* p = (const float4*)(X + (size_t)row * EMB + kt * 64 + ci * 8);
    float vv[8];
    *(float4*)&vv[0] = p[0];
    *(float4*)&vv[4] = p[1];
    uint4 h = conv8h(vv);
    int mt = row >> 7, r = row & 127;
    uint32_t off = swz(r * 128 + ci * 16);
    size_t base = ((size_t)(mt * KT + kt)) * TILE_ELEMS;
    *(uint4*)((char*)g_xf + base * 2 + off) = h;
}

__global__ __launch_bounds__(256) void split_w_kernel(const float* __restrict__ Wq,
                                                      const float* __restrict__ Wk,
                                                      const float* __restrict__ Wv,
                                                      const float* __restrict__ Wu,
                                                      const float* __restrict__ Wo) {
    int i = blockIdx.x * 256 + threadIdx.x;
    int row = i >> 7, c = i & 127;
    int widx = row >> 10, r = row & 1023;
    int kt = c >> 3, ci = c & 7;
    const float* W = (widx == 0) ? Wq : (widx == 1) ? Wk : (widx == 2) ? Wv : (widx == 3) ? Wu : Wo;
    const float4* p = (const float4*)(W + (size_t)r * EMB + kt * 64 + ci * 8);
    float vv[8];
    *(float4*)&vv[0] = p[0];
    *(float4*)&vv[4] = p[1];
    uint4 h = conv8h(vv);
    int nt = r >> 7, rr = r & 127;
    uint32_t off = swz(rr * 128 + ci * 16);
    size_t base = (size_t)widx * WSZ + ((size_t)(nt * KT + kt)) * TILE_ELEMS;
    *(uint4*)((char*)g_wf + base * 2 + off) = h;
}

__global__ void zero_kv_kernel() {
    int i = blockIdx.x * 256 + threadIdx.x;
    if (i < NBH * HD * HD) g_kvT[i] = 0.0f;
}

// ---------------- proj GEMM: 128x128 CTA, BK=64, 3-stage, 1 sync/chunk ----
__global__ __launch_bounds__(256, 2) void proj_mma() {
    extern __shared__ char sm[];
    uint32_t sb = s2u(sm);
    const int tid = threadIdx.x, lane = tid & 31, wid = tid >> 5;
    const int mt = blockIdx.x, nt = blockIdx.y, z = blockIdx.z;
    const int warpM = (wid >> 2) * 64;
    const int warpN = (wid & 3) * 32;
    const f16* Bg = g_wf + (size_t)z * WSZ;

    auto load_stage = [&](int s, int kc) {
        uint32_t d = sb + s * STAGE_BYTES;
        size_t at = ((size_t)(mt * KT + kc)) * TILE_ELEMS;
        size_t bt = ((size_t)(nt * KT + kc)) * TILE_ELEMS;
        const char* srcs[2] = {(const char*)(g_xf + at), (const char*)(Bg + bt)};
#pragma unroll
        for (int blk = 0; blk < 2; blk++)
#pragma unroll
            for (int i = 0; i < 4; i++)
                cpa16(d + blk * TILE_BYTES + i * 4096 + tid * 16,
                      srcs[blk] + i * 4096 + tid * 16);
        cpa_commit();
    };

    float acc[4][4][4];
#pragma unroll
    for (int i = 0; i < 4; i++)
#pragma unroll
        for (int j = 0; j < 4; j++)
#pragma unroll
            for (int e = 0; e < 4; e++) acc[i][j][e] = 0.0f;

    const int aRow = warpM + (lane & 15);
    const int aKg  = (lane >> 4);
    const int bRow = warpN + ((lane >> 4) << 3) + (lane & 7);
    const int bKg  = ((lane >> 3) & 1);

    load_stage(0, 0);
    load_stage(1, 1);

    for (int kc = 0; kc < KT; kc++) {
        int cur = kc % STAGES;
        if (kc + 1 < KT) cpa_wait1(); else cpa_wait0();
        __syncthreads();
        if (kc + 2 < KT) load_stage((kc + 2) % STAGES, kc + 2);

        uint32_t A = sb + cur * STAGE_BYTES;
        uint32_t B = A + TILE_BYTES;

#pragma unroll
        for (int kk = 0; kk < 4; kk++) {
            uint32_t aX[4][4], bF[4][2];
#pragma unroll
            for (int i = 0; i < 4; i++)
                ldsm4(aX[i][0], aX[i][1], aX[i][2], aX[i][3],
                      A + swz((aRow + i * 16) * 128 + (kk * 2 + aKg) * 16));
#pragma unroll
            for (int jj = 0; jj < 2; jj++) {
                uint32_t boff = swz((bRow + jj * 16) * 128 + (kk * 2 + bKg) * 16);
                ldsm4(bF[2 * jj][0], bF[2 * jj][1],
                      bF[2 * jj + 1][0], bF[2 * jj + 1][1], B + boff);
            }
#pragma unroll
            for (int i = 0; i < 4; i++)
#pragma unroll
                for (int j = 0; j < 4; j++)
                    mma16816(acc[i][j], aX[i][0], aX[i][1], aX[i][2], aX[i][3],
                             bF[j][0], bF[j][1]);
        }
    }

    // ---- epilogue: all z write head-tiled; q/k/v hi/lo fp16, u fp32 ----
    f16* dh = (z == 0) ? g_qh : (z == 1) ? g_kh : g_vh;
    f16* dl = (z == 0) ? g_ql : (z == 1) ? g_kl : g_vl;
#pragma unroll
    for (int i = 0; i < 4; i++) {
#pragma unroll
        for (int j = 0; j < 4; j++) {
#pragma unroll
            for (int half = 0; half < 2; half++) {
                int r = warpM + i * 16 + (lane >> 2) + half * 8;
                int c = warpN + j * 8 + (lane & 3) * 2;
                int h = c >> 6, cin = c & 63;
                float v0 = acc[i][j][half * 2 + 0];
                float v1 = acc[i][j][half * 2 + 1];
                size_t tile = (size_t)mt * 16 + (nt * 2 + h);
                if (z == 3) {
                    v0 = v0 / (1.f + expf(-v0));
                    v1 = v1 / (1.f + expf(-v1));
                    *(float2*)(g_uF + tile * TILE_ELEMS + r * 64 + cin) =
                        make_float2(v0, v1);
                } else {
                    if (z <= 1) {
                        v0 = fmaxf(v0, 0.f) * 0.125f;
                        v1 = fmaxf(v1, 0.f) * 0.125f;
                    }
                    uint32_t hv, lv;
                    split2h(v0, v1, hv, lv);
                    size_t base = tile * (size_t)TILE_BYTES;
                    uint32_t off = swz(r * 128 + cin * 2);
                    *(uint32_t*)((char*)dh + base + off) = hv;
                    *(uint32_t*)((char*)dl + base + off) = lv;
                }
            }
        }
    }
}

// ---------------- fin GEMM: single-product, 3-stage, 1 sync/chunk ---------
__global__ __launch_bounds__(256, 2) void fin_mma(float* __restrict__ C) {
    extern __shared__ char sm[];
    uint32_t sb = s2u(sm);
    const int tid = threadIdx.x, lane = tid & 31, wid = tid >> 5;
    const int mt = blockIdx.x, nt = blockIdx.y;
    const int warpM = (wid >> 2) * 64;
    const int warpN = (wid & 3) * 32;
    const f16* Bg = g_wf + (size_t)4 * WSZ;

    auto load_stage = [&](int s, int kc) {
        uint32_t d = sb + s * STAGE_BYTES;
        size_t at = ((size_t)(mt * KT + kc)) * TILE_ELEMS;
        size_t bt = ((size_t)(nt * KT + kc)) * TILE_ELEMS;
        const char* srcs[2] = {(const char*)(g_yf + at), (const char*)(Bg + bt)};
#pragma unroll
        for (int blk = 0; blk < 2; blk++)
#pragma unroll
            for (int i = 0; i < 4; i++)
                cpa16(d + blk * TILE_BYTES + i * 4096 + tid * 16,
                      srcs[blk] + i * 4096 + tid * 16);
        cpa_commit();
    };

    float acc[4][4][4];
#pragma unroll
    for (int i = 0; i < 4; i++)
#pragma unroll
        for (int j = 0; j < 4; j++)
#pragma unroll
            for (int e = 0; e < 4; e++) acc[i][j][e] = 0.0f;

    const int aRow = warpM + (lane & 15);
    const int aKg  = (lane >> 4);
    const int bRow = warpN + ((lane >> 4) << 3) + (lane & 7);
    const int bKg  = ((lane >> 3) & 1);

    load_stage(0, 0);
    load_stage(1, 1);

    for (int kc = 0; kc < KT; kc++) {
        int cur = kc % STAGES;
        if (kc + 1 < KT) cpa_wait1(); else cpa_wait0();
        __syncthreads();
        if (kc + 2 < KT) load_stage((kc + 2) % STAGES, kc + 2);

        uint32_t A = sb + cur * STAGE_BYTES;
        uint32_t B = A + TILE_BYTES;

#pragma unroll
        for (int kk = 0; kk < 4; kk++) {
            uint32_t aX[4][4], bF[4][2];
#pragma unroll
            for (int i = 0; i < 4; i++)
                ldsm4(aX[i][0], aX[i][1], aX[i][2], aX[i][3],
                      A + swz((aRow + i * 16) * 128 + (kk * 2 + aKg) * 16));
#pragma unroll
            for (int jj = 0; jj < 2; jj++) {
                uint32_t boff = swz((bRow + jj * 16) * 128 + (kk * 2 + bKg) * 16);
                ldsm4(bF[2 * jj][0], bF[2 * jj][1],
                      bF[2 * jj + 1][0], bF[2 * jj + 1][1], B + boff);
            }
#pragma unroll
            for (int i = 0; i < 4; i++)
#pragma unroll
                for (int j = 0; j < 4; j++)
                    mma16816(acc[i][j], aX[i][0], aX[i][1], aX[i][2], aX[i][3],
                             bF[j][0], bF[j][1]);
        }
    }

#pragma unroll
    for (int i = 0; i < 4; i++)
#pragma unroll
        for (int j = 0; j < 4; j++)
#pragma unroll
            for (int half = 0; half < 2; half++) {
                int row = mt * 128 + warpM + i * 16 + (lane >> 2) + half * 8;
                int col = nt * 128 + warpN + j * 8 + (lane & 3) * 2;
                *(float2*)(C + (size_t)row * EMB + col) =
                    make_float2(acc[i][j][half * 2], acc[i][j][half * 2 + 1]);
            }
}

// ---------------- kv via mma + ldmatrix.trans (head-tiled k/v inputs) ------
// kvT[vb][ka] += sum_l v[l,vb] * k[l,ka]
__global__ __launch_bounds__(128, 3) void kv_mma() {
    extern __shared__ char sm[];
    uint32_t sb = s2u(sm);
    const int tid = threadIdx.x, lane = tid & 31, wid = tid >> 5;
    const int bh = blockIdx.x, split = blockIdx.y;
    const int b = bh >> 4, h = bh & 15;
    const int warpM = (wid >> 1) * 32;   // vb
    const int warpN = (wid & 1) * 32;    // ka

    auto load_stage = [&](int s, int ch) {
        int g = split * 8 + ch;                 // 64-row half-tile index, 0..63
        int mt = b * 32 + (g >> 1);
        size_t tb = ((size_t)(mt * 16 + h)) * TILE_BYTES + (size_t)(g & 1) * 8192;
        const char* srcs[4] = {(const char*)g_vh + tb, (const char*)g_vl + tb,
                               (const char*)g_kh + tb, (const char*)g_kl + tb};
        uint32_t d = sb + s * 32768;
#pragma unroll
        for (int blk = 0; blk < 4; blk++)
#pragma unroll
            for (int i = 0; i < 4; i++)
                cpa16(d + blk * 8192 + i * 2048 + tid * 16,
                      srcs[blk] + i * 2048 + tid * 16);
        cpa_commit();
    };

    float acc[2][4][4];
#pragma unroll
    for (int i = 0; i < 2; i++)
#pragma unroll
        for (int j = 0; j < 4; j++)
#pragma unroll
            for (int e = 0; e < 4; e++) acc[i][j][e] = 0.0f;

    // trans-ldmatrix lane->source mapping (source rows = l, cols = head dim)
    const int rA  = (lane & 7) + ((lane >> 4) << 3);     // A: m-matrices pairs
    const int cbA = ((lane >> 3) & 1) << 4;
    const int rB  = (lane & 7) + (((lane >> 3) & 1) << 3);  // B: k-matrices pairs
    const int cbB = ((lane >> 4) & 1) << 4;

    load_stage(0, 0);
    load_stage(1, 1);

    for (int ch = 0; ch < 8; ch++) {
        int cur = ch & 1;
        if (ch + 1 < 8) cpa_wait1(); else cpa_wait0();
        __syncthreads();
        uint32_t Avh = sb + cur * 32768;
        uint32_t Avl = Avh + 8192, Bkh = Avh + 16384, Bkl = Avh + 24576;

#pragma unroll
        for (int kk = 0; kk < 4; kk++) {
            uint32_t avh[2][4], avl[2][4], bkh[4][2], bkl[4][2];
#pragma unroll
            for (int i = 0; i < 2; i++) {
                uint32_t aoff = swz((kk * 16 + rA) * 128 + (warpM + i * 16) * 2 + cbA);
                ldsm4t(avh[i][0], avh[i][1], avh[i][2], avh[i][3], Avh + aoff);
                ldsm4t(avl[i][0], avl[i][1], avl[i][2], avl[i][3], Avl + aoff);
            }
#pragma unroll
            for (int jj = 0; jj < 2; jj++) {
                uint32_t boff = swz((kk * 16 + rB) * 128 + (warpN + jj * 16) * 2 + cbB);
                ldsm4t(bkh[2 * jj][0], bkh[2 * jj][1],
                       bkh[2 * jj + 1][0], bkh[2 * jj + 1][1], Bkh + boff);
                ldsm4t(bkl[2 * jj][0], bkl[2 * jj][1],
                       bkl[2 * jj + 1][0], bkl[2 * jj + 1][1], Bkl + boff);
            }
#pragma unroll
            for (int i = 0; i < 2; i++)
#pragma unroll
                for (int j = 0; j < 4; j++) {
                    mma16816(acc[i][j], avh[i][0], avh[i][1], avh[i][2], avh[i][3],
                             bkh[j][0], bkh[j][1]);
                    mma16816(acc[i][j], avh[i][0], avh[i][1], avh[i][2], avh[i][3],
                             bkl[j][0], bkl[j][1]);
                    mma16816(acc[i][j], avl[i][0], avl[i][1], avl[i][2], avl[i][3],
                             bkh[j][0], bkh[j][1]);
                }
        }
        __syncthreads();
        if (ch + 2 < 8) load_stage(cur, ch + 2);
    }

    float* kvp = g_kvT + (size_t)bh * 4096;
#pragma unroll
    for (int i = 0; i < 2; i++)
#pragma unroll
        for (int j = 0; j < 4; j++)
#pragma unroll
            for (int half = 0; half < 2; half++) {
                int row = warpM + i * 16 + (lane >> 2) + half * 8;
                int col = warpN + j * 8 + (lane & 3) * 2;
                atomicAdd(kvp + row * 64 + col,     acc[i][j][half * 2]);
                atomicAdd(kvp + row * 64 + col + 1, acc[i][j][half * 2 + 1]);
            }
}

// ---------------- kvT fp32 -> hi/lo fp16 swizzled tiles ----------------
__global__ __launch_bounds__(256) void kv_split() {
    int bh = blockIdx.x, t = threadIdx.x;
    int row = t >> 2, c0 = (t & 3) * 16;
    const float* src = g_kvT + (size_t)bh * 4096 + row * 64 + c0;
    float vv[16];
#pragma unroll
    for (int g = 0; g < 4; g++) *(float4*)&vv[g * 4] = ((const float4*)src)[g];
    size_t base = ((size_t)bh * 4096) * 2;
#pragma unroll
    for (int g = 0; g < 2; g++) {
        uint4 hq, lq;
        split8h(&vv[g * 8], hq, lq);
        uint32_t off = swz(row * 128 + c0 * 2 + g * 16);
        *(uint4*)((char*)g_kvh + base + off) = hq;
        *(uint4*)((char*)g_kvl + base + off) = lq;
    }
}

// ---------------- out = q@kv; SRMSNorm; *u; write fp16 y tiles ----------------
__global__ __launch_bounds__(256) void out_mma() {
    extern __shared__ char sm[];
    uint32_t sb = s2u(sm);
    const int tid = threadIdx.x, lane = tid & 31, wid = tid >> 5;
    const int mt = blockIdx.x, h = blockIdx.y;
    const int bh = (mt >> 5) * 16 + h;
    const size_t qbase = ((size_t)mt * 16 + h) * TILE_ELEMS * 2;    // bytes
    const size_t kvbase = ((size_t)bh * 4096) * 2;

    // single-shot loads: qh(16K) ql(16K) kvh(8K) kvl(8K)
#pragma unroll
    for (int i = 0; i < 4; i++) {
        cpa16(sb + i * 4096 + tid * 16, (const char*)g_qh + qbase + i * 4096 + tid * 16);
        cpa16(sb + 16384 + i * 4096 + tid * 16,
              (const char*)g_ql + qbase + i * 4096 + tid * 16);
    }
#pragma unroll
    for (int i = 0; i < 2; i++) {
        cpa16(sb + 32768 + i * 4096 + tid * 16,
              (const char*)g_kvh + kvbase + i * 4096 + tid * 16);
        cpa16(sb + 40960 + i * 4096 + tid * 16,
              (const char*)g_kvl + kvbase + i * 4096 + tid * 16);
    }
    cpa_commit();
    cpa_wait0();
    __syncthreads();

    const int warpM = wid * 16;
    const int aRow = warpM + (lane & 15);
    const int aKg  = (lane >> 4);
    const int bRow = ((lane >> 4) << 3) + (lane & 7);
    const int bKg  = ((lane >> 3) & 1);
    const uint32_t Qh = sb, Ql = sb + 16384, Kh = sb + 32768, Kl = sb + 40960;

    float acc[8][4];
#pragma unroll
    for (int j = 0; j < 8; j++)
#pragma unroll
        for (int e = 0; e < 4; e++) acc[j][e] = 0.0f;

#pragma unroll
    for (int kk = 0; kk < 4; kk++) {
        uint32_t aqh[4], aql[4], bvh[8][2], bvl[8][2];
        uint32_t aoff = swz(aRow * 128 + (kk * 2 + aKg) * 16);
        ldsm4(aqh[0], aqh[1], aqh[2], aqh[3], Qh + aoff);
        ldsm4(aql[0], aql[1], aql[2], aql[3], Ql + aoff);
#pragma unroll
        for (int jj = 0; jj < 4; jj++) {
            uint32_t boff = swz((jj * 16 + bRow) * 128 + (kk * 2 + bKg) * 16);
            ldsm4(bvh[2 * jj][0], bvh[2 * jj][1],
                  bvh[2 * jj + 1][0], bvh[2 * jj + 1][1], Kh + boff);
            ldsm4(bvl[2 * jj][0], bvl[2 * jj][1],
                  bvl[2 * jj + 1][0], bvl[2 * jj + 1][1], Kl + boff);
        }
#pragma unroll
        for (int j = 0; j < 8; j++) {
            mma16816(acc[j], aqh[0], aqh[1], aqh[2], aqh[3], bvh[j][0], bvh[j][1]);
            mma16816(acc[j], aqh[0], aqh[1], aqh[2], aqh[3], bvl[j][0], bvl[j][1]);
            mma16816(acc[j], aql[0], aql[1], aql[2], aql[3], bvh[j][0], bvh[j][1]);
        }
    }

    // row-wise SRMSNorm + u-multiply + fp16 tiled y store
    const size_t ub = ((size_t)mt * 16 + h) * TILE_ELEMS;           // fp32 elems
    const size_t yb = ((size_t)mt * 16 + h) * TILE_ELEMS * 2;       // bytes
#pragma unroll
    for (int half = 0; half < 2; half++) {
        float ss = 0.0f;
#pragma unroll
        for (int j = 0; j < 8; j++)
            ss += acc[j][half * 2] * acc[j][half * 2] +
                  acc[j][half * 2 + 1] * acc[j][half * 2 + 1];
        ss += __shfl_xor_sync(0xFFFFFFFF, ss, 1);
        ss += __shfl_xor_sync(0xFFFFFFFF, ss, 2);
        float n = sqrtf(ss) * 0.125f;
        float inv = 1.0f / fmaxf(n, 1e-12f);
        int r = warpM + (lane >> 2) + half * 8;
#pragma unroll
        for (int j = 0; j < 8; j++) {
            int c = j * 8 + (lane & 3) * 2;
            float2 uv = *(const float2*)(g_uF + ub + r * 64 + c);
            float y0 = acc[j][half * 2] * inv * uv.x;
            float y1 = acc[j][half * 2 + 1] * inv * uv.y;
            __half2 yy = __floats2half2_rn(y0, y1);
            *(__half2*)((char*)g_yf + yb + swz(r * 128 + c * 2)) = yy;
        }
    }
}

// ---------------------------------------------------------------------------
extern "C" void kernel_launch(void* const* d_in, const int* in_sizes, int n_in,
                              void* d_out, int out_size) {
    const float* x  = (const float*)d_in[0];
    const float* Wq = (const float*)d_in[1];
    const float* Wk = (const float*)d_in[2];
    const float* Wv = (const float*)d_in[3];
    const float* Wu = (const float*)d_in[4];
    const float* Wo = (const float*)d_in[5];
    float* out = (float*)d_out;

    cudaFuncSetAttribute(proj_mma, cudaFuncAttributeMaxDynamicSharedMemorySize, GSMEM);
    cudaFuncSetAttribute(fin_mma,  cudaFuncAttributeMaxDynamicSharedMemorySize, GSMEM);
    cudaFuncSetAttribute(kv_mma,   cudaFuncAttributeMaxDynamicSharedMemorySize, 65536);
    cudaFuncSetAttribute(out_mma,  cudaFuncAttributeMaxDynamicSharedMemorySize, 49152);

    split_x_kernel<<<8192, 256>>>(x);
    split_w_kernel<<<2560, 256>>>(Wq, Wk, Wv, Wu, Wo);
    zero_kv_kernel<<<1024, 256>>>();
    proj_mma<<<dim3(128, 8, 4), 256, GSMEM>>>();
    kv_mma<<<dim3(NBH, 8), 128, 65536>>>();
    kv_split<<<NBH, 256>>>();
    out_mma<<<dim3(128, 16), 256, 49152>>>();
    fin_mma<<<dim3(128, 8), 256, GSMEM>>>(out);
}